// round 8
// baseline (speedup 1.0000x reference)
#include <cuda_runtime.h>
#include <cuda_bf16.h>
#include <math.h>
#include <stdint.h>

// GNNEncoder: N=100000 nodes, E=800000 edges, 384 -> 256 -> 256
#define MAXN 100000
#define MAXE 800000
#define HID  256
#define IN_DIM_C 384
#define BN_EPS 1e-5f

// ---------------- device scratch ----------------
__device__ float g_h[(size_t)MAXN * HID];
__device__ float g_a[(size_t)MAXN * HID];
__device__ int   g_deg[MAXN];
__device__ int   g_fill[MAXN];
__device__ int   g_rowp[MAXN + 1];
__device__ int   g_blksum[512];
__device__ int   g_blkoff[512];
__device__ int   g_esrc[MAXE];
__device__ float g_ecoef[MAXE];
__device__ float g_dinv[MAXN];
__device__ float g_invdeg[MAXN];
__device__ float g_stats[4 * HID];   // sum1, sq1, sum2, sq2
__device__ float g_coef[4 * HID];    // ga1, bb1, ga2, bb2
// pre-split weights (bf16 hi/lo), layout [K][N]
__device__ __nv_bfloat16 g_W1h[IN_DIM_C * HID];
__device__ __nv_bfloat16 g_W1l[IN_DIM_C * HID];
__device__ __nv_bfloat16 g_W2h[HID * HID];
__device__ __nv_bfloat16 g_W2l[HID * HID];
// pre-split activations (bf16 hi/lo), layout [M][K], K = 384 (L1) or 256 (L2)
__device__ __nv_bfloat16 g_Ah[(size_t)MAXN * IN_DIM_C];
__device__ __nv_bfloat16 g_Al[(size_t)MAXN * IN_DIM_C];

// ---------------- float4 helpers ----------------
__device__ __forceinline__ float4 f4fma(float4 a, float s, float4 b) {
    b.x = fmaf(a.x, s, b.x); b.y = fmaf(a.y, s, b.y);
    b.z = fmaf(a.z, s, b.z); b.w = fmaf(a.w, s, b.w);
    return b;
}
__device__ __forceinline__ void f4acc(float4& d, float4 v) {
    d.x += v.x; d.y += v.y; d.z += v.z; d.w += v.w;
}
__device__ __forceinline__ void f4accsq(float4& d, float4 v) {
    d.x = fmaf(v.x, v.x, d.x); d.y = fmaf(v.y, v.y, d.y);
    d.z = fmaf(v.z, v.z, d.z); d.w = fmaf(v.w, v.w, d.w);
}
__device__ __forceinline__ void split4dev(float4 v, __nv_bfloat162& h01, __nv_bfloat162& h23,
                                          __nv_bfloat162& l01, __nv_bfloat162& l23) {
    __nv_bfloat16 hx = __float2bfloat16(v.x);
    __nv_bfloat16 hy = __float2bfloat16(v.y);
    __nv_bfloat16 hz = __float2bfloat16(v.z);
    __nv_bfloat16 hw = __float2bfloat16(v.w);
    h01 = __halves2bfloat162(hx, hy);
    h23 = __halves2bfloat162(hz, hw);
    l01 = __halves2bfloat162(__float2bfloat16(v.x - __bfloat162float(hx)),
                             __float2bfloat16(v.y - __bfloat162float(hy)));
    l23 = __halves2bfloat162(__float2bfloat16(v.z - __bfloat162float(hz)),
                             __float2bfloat16(v.w - __bfloat162float(hw)));
}

// ---------------- init / degree ----------------
__global__ void zero_kernel(int N) {
    int i = blockIdx.x * blockDim.x + threadIdx.x;
    if (i < N) { g_deg[i] = 0; g_fill[i] = 0; }
    if (i < 4 * HID) g_stats[i] = 0.0f;
}

__global__ void deg_count(const int* __restrict__ dst, int E) {
    int i = blockIdx.x * blockDim.x + threadIdx.x;
    if (i < E) atomicAdd(&g_deg[dst[i]], 1);
}

// ---------------- weight pre-split ----------------
__global__ void wsplit(const float* __restrict__ W1, const float* __restrict__ W2) {
    int i = blockIdx.x * blockDim.x + threadIdx.x;
    if (i < IN_DIM_C * HID) {
        float v = W1[i];
        __nv_bfloat16 h = __float2bfloat16(v);
        g_W1h[i] = h;
        g_W1l[i] = __float2bfloat16(v - __bfloat162float(h));
    }
    if (i < HID * HID) {
        float v = W2[i];
        __nv_bfloat16 h = __float2bfloat16(v);
        g_W2h[i] = h;
        g_W2l[i] = __float2bfloat16(v - __bfloat162float(h));
    }
}

// ---------------- activation pre-split (optionally fused BN+ReLU) ----------------
// plain: Ahl = split(src).  BN mode: Ahl = split(relu(src*ga + bb)), coefs per column.
template<bool BNA>
__global__ __launch_bounds__(256) void convertA(const float* __restrict__ src,
                                                const float* __restrict__ ga,
                                                const float* __restrict__ bb,
                                                int total4, int kq) {   // kq = K/4
    int i = blockIdx.x * blockDim.x + threadIdx.x;
    if (i >= total4) return;
    float4 v = ((const float4*)src)[i];
    if (BNA) {
        int c4 = i % kq;
        float4 g = ((const float4*)ga)[c4];
        float4 b = ((const float4*)bb)[c4];
        v.x = fmaxf(0.f, fmaf(v.x, g.x, b.x));
        v.y = fmaxf(0.f, fmaf(v.y, g.y, b.y));
        v.z = fmaxf(0.f, fmaf(v.z, g.z, b.z));
        v.w = fmaxf(0.f, fmaf(v.w, g.w, b.w));
    }
    __nv_bfloat162 h01, h23, l01, l23;
    split4dev(v, h01, h23, l01, l23);
    uint2 hp, lp;
    hp.x = *(uint32_t*)&h01; hp.y = *(uint32_t*)&h23;
    lp.x = *(uint32_t*)&l01; lp.y = *(uint32_t*)&l23;
    ((uint2*)g_Ah)[i] = hp;
    ((uint2*)g_Al)[i] = lp;
}

// ---------------- scan of g_deg -> g_rowp + dinv/invdeg (fused) ----------------
__global__ void scan1(int N) {
    __shared__ int s[256];
    int t = threadIdx.x;
    int i = blockIdx.x * 256 + t;
    int v = (i < N) ? g_deg[i] : 0;
    if (i < N) {
        float dg = (float)v + 1.0f;
        g_dinv[i]   = rsqrtf(dg);
        g_invdeg[i] = 1.0f / dg;
    }
    s[t] = v; __syncthreads();
    #pragma unroll
    for (int off = 1; off < 256; off <<= 1) {
        int x = (t >= off) ? s[t - off] : 0;
        __syncthreads();
        s[t] += x;
        __syncthreads();
    }
    if (i < N) g_rowp[i] = s[t] - v;             // exclusive
    if (t == 255) g_blksum[blockIdx.x] = s[t];
}
__global__ void scan2(int nb) {
    __shared__ int s[512];
    int t = threadIdx.x;
    int v = (t < nb) ? g_blksum[t] : 0;
    s[t] = v; __syncthreads();
    #pragma unroll
    for (int off = 1; off < 512; off <<= 1) {
        int x = (t >= off) ? s[t - off] : 0;
        __syncthreads();
        s[t] += x;
        __syncthreads();
    }
    g_blkoff[t] = s[t] - v;
}
__global__ void scan3(int N, int E) {
    int i = blockIdx.x * 256 + threadIdx.x;
    if (i < N) g_rowp[i] += g_blkoff[i >> 8];
    if (i == 0) g_rowp[N] = E;
}

// ---------------- CSR fill ----------------
__global__ void csr_fill(const int* __restrict__ src, const int* __restrict__ dst, int E) {
    int e = blockIdx.x * blockDim.x + threadIdx.x;
    if (e >= E) return;
    int s = src[e], d = dst[e];
    int pos = g_rowp[d] + atomicAdd(&g_fill[d], 1);
    g_esrc[pos]  = s;
    g_ecoef[pos] = g_dinv[s] * g_dinv[d];
}

// ---------------- tensor-core GEMM (bf16x3, all-bf16 operands, cp.async) -------------
#define TBM 128
#define TBN 128
#define TBK 32
#define APAD 40      // row = 80B (16B multiple, cp.async friendly)
#define BPAD 136     // row = 272B

#define LDSM4(R, addr) \
    asm volatile("ldmatrix.sync.aligned.m8n8.x4.shared.b16 {%0,%1,%2,%3}, [%4];" \
        : "=r"((R)[0]), "=r"((R)[1]), "=r"((R)[2]), "=r"((R)[3]) : "r"(addr))
#define LDSM4T(R, addr) \
    asm volatile("ldmatrix.sync.aligned.m8n8.x4.trans.shared.b16 {%0,%1,%2,%3}, [%4];" \
        : "=r"((R)[0]), "=r"((R)[1]), "=r"((R)[2]), "=r"((R)[3]) : "r"(addr))
#define MMA16816(d, a, b0, b1) \
    asm volatile("mma.sync.aligned.m16n8k16.row.col.f32.bf16.bf16.f32 " \
        "{%0,%1,%2,%3},{%4,%5,%6,%7},{%8,%9},{%0,%1,%2,%3};" \
        : "+f"((d)[0]), "+f"((d)[1]), "+f"((d)[2]), "+f"((d)[3]) \
        : "r"((a)[0]), "r"((a)[1]), "r"((a)[2]), "r"((a)[3]), "r"(b0), "r"(b1))
#define CPASYNC16(dst, src, sz) \
    asm volatile("cp.async.cg.shared.global [%0], [%1], 16, %2;" \
        :: "r"(dst), "l"(src), "r"(sz) : "memory")

__global__ __launch_bounds__(256, 2) void mma_gemm(
    const __nv_bfloat16* __restrict__ Ah, const __nv_bfloat16* __restrict__ Al,
    const __nv_bfloat16* __restrict__ Bh, const __nv_bfloat16* __restrict__ Bl,
    float* __restrict__ C, int M, int K)
{
    __shared__ __nv_bfloat16 sAh[2][TBM][APAD];
    __shared__ __nv_bfloat16 sAl[2][TBM][APAD];
    __shared__ __nv_bfloat16 sBh[2][TBK][BPAD];
    __shared__ __nv_bfloat16 sBl[2][TBK][BPAD];

    int tid = threadIdx.x;
    int warp = tid >> 5, lane = tid & 31;
    int wm = warp >> 2, wn = warp & 3;           // 2x4 warp grid, warp tile m64 x n32
    int block_row = blockIdx.x * TBM;
    int block_col = blockIdx.y * TBN;

    float acc[4][4][4];
    #pragma unroll
    for (int i = 0; i < 4; i++)
        #pragma unroll
        for (int j = 0; j < 4; j++)
            #pragma unroll
            for (int k = 0; k < 4; k++) acc[i][j][k] = 0.0f;

    auto issueStage = [&](int st, int k0) {
        // A tiles: 128 rows x 32 bf16 (64B) -> 4 granules/row, 512 granules each
        #pragma unroll
        for (int q = 0; q < 2; q++) {
            int g = tid * 2 + q;
            int row = g >> 2, c16 = g & 3;
            int grow = block_row + row;
            int sz = (grow < M) ? 16 : 0;
            const __nv_bfloat16* ph = Ah + (size_t)grow * K + k0 + c16 * 8;
            const __nv_bfloat16* pl = Al + (size_t)grow * K + k0 + c16 * 8;
            uint32_t dh = (uint32_t)__cvta_generic_to_shared(&sAh[st][row][c16 * 8]);
            uint32_t dl = (uint32_t)__cvta_generic_to_shared(&sAl[st][row][c16 * 8]);
            CPASYNC16(dh, ph, sz);
            CPASYNC16(dl, pl, sz);
        }
        // B tiles: 32 rows x 128 bf16 (256B) -> 16 granules/row, 512 granules each
        #pragma unroll
        for (int q = 0; q < 2; q++) {
            int g = tid * 2 + q;
            int row = g >> 4, c16 = g & 15;
            const __nv_bfloat16* ph = Bh + (size_t)(k0 + row) * HID + block_col + c16 * 8;
            const __nv_bfloat16* pl = Bl + (size_t)(k0 + row) * HID + block_col + c16 * 8;
            uint32_t dh = (uint32_t)__cvta_generic_to_shared(&sBh[st][row][c16 * 8]);
            uint32_t dl = (uint32_t)__cvta_generic_to_shared(&sBl[st][row][c16 * 8]);
            CPASYNC16(dh, ph, 16);
            CPASYNC16(dl, pl, 16);
        }
        asm volatile("cp.async.commit_group;" ::: "memory");
    };

    auto mmaStage = [&](int st) {
        #pragma unroll
        for (int ks = 0; ks < 2; ks++) {
            uint32_t afh[4][4], afl[4][4], bfh[2][4], bfl[2][4];
            #pragma unroll
            for (int mi = 0; mi < 4; mi++) {
                int r = wm * 64 + mi * 16 + (lane & 15);
                int c = ks * 16 + (lane >> 4) * 8;
                uint32_t ah = (uint32_t)__cvta_generic_to_shared(&sAh[st][r][c]);
                uint32_t al = (uint32_t)__cvta_generic_to_shared(&sAl[st][r][c]);
                LDSM4(afh[mi], ah);
                LDSM4(afl[mi], al);
            }
            #pragma unroll
            for (int ni = 0; ni < 2; ni++) {
                int r = ks * 16 + (lane & 15);
                int c = wn * 32 + ni * 16 + (lane >> 4) * 8;
                uint32_t bh = (uint32_t)__cvta_generic_to_shared(&sBh[st][r][c]);
                uint32_t bl = (uint32_t)__cvta_generic_to_shared(&sBl[st][r][c]);
                LDSM4T(bfh[ni], bh);
                LDSM4T(bfl[ni], bl);
            }
            #pragma unroll
            for (int mi = 0; mi < 4; mi++)
                #pragma unroll
                for (int n8 = 0; n8 < 4; n8++) {
                    uint32_t bh0 = bfh[n8 >> 1][(n8 & 1) * 2];
                    uint32_t bh1 = bfh[n8 >> 1][(n8 & 1) * 2 + 1];
                    uint32_t bl0 = bfl[n8 >> 1][(n8 & 1) * 2];
                    uint32_t bl1 = bfl[n8 >> 1][(n8 & 1) * 2 + 1];
                    MMA16816(acc[mi][n8], afh[mi], bh0, bh1);
                    MMA16816(acc[mi][n8], afl[mi], bh0, bh1);
                    MMA16816(acc[mi][n8], afh[mi], bl0, bl1);
                }
        }
    };

    int nIters = K / TBK;
    issueStage(0, 0);
    for (int it = 0; it < nIters; it++) {
        int cur = it & 1;
        bool more = (it + 1 < nIters);
        if (more) {
            issueStage(cur ^ 1, (it + 1) * TBK);
            asm volatile("cp.async.wait_group 1;" ::: "memory");
        } else {
            asm volatile("cp.async.wait_group 0;" ::: "memory");
        }
        __syncthreads();
        mmaStage(cur);
        __syncthreads();
    }

    #pragma unroll
    for (int mi = 0; mi < 4; mi++) {
        #pragma unroll
        for (int n8 = 0; n8 < 4; n8++) {
            int col = block_col + wn * 32 + n8 * 8 + (lane & 3) * 2;
            #pragma unroll
            for (int h = 0; h < 2; h++) {
                int row = block_row + wm * 64 + mi * 16 + (lane >> 2) + h * 8;
                if (row < M) {
                    *(float2*)(C + (size_t)row * HID + col) =
                        make_float2(acc[mi][n8][h * 2], acc[mi][n8][h * 2 + 1]);
                }
            }
        }
    }
}

// ---------------- pull aggregation + fused BN stats (unroll-4, MLP=8) ----------------
__global__ __launch_bounds__(256) void aggregate(
    const float* __restrict__ h, const float* __restrict__ bias,
    float* __restrict__ agg, float* __restrict__ sum, float* __restrict__ sq, int N)
{
    int lane = threadIdx.x & 31;
    int w    = threadIdx.x >> 5;
    int wId  = (blockIdx.x << 3) + w;
    int nW   = gridDim.x << 3;

    float4 bv0 = ((const float4*)bias)[lane];
    float4 bv1 = ((const float4*)bias)[32 + lane];
    float4 cs0 = make_float4(0,0,0,0), cq0 = make_float4(0,0,0,0);
    float4 cs1 = make_float4(0,0,0,0), cq1 = make_float4(0,0,0,0);

    for (int d = wId; d < N; d += nW) {
        int beg = g_rowp[d], end = g_rowp[d + 1];
        float id = g_invdeg[d];
        const float4* hd = (const float4*)(h + (size_t)d * HID);
        float4 a0 = f4fma(hd[lane],      id, bv0);
        float4 a1 = f4fma(hd[32 + lane], id, bv1);

        int j = beg;
        for (; j + 4 <= end; j += 4) {
            int   s0 = g_esrc[j],     s1 = g_esrc[j + 1];
            int   s2 = g_esrc[j + 2], s3 = g_esrc[j + 3];
            float c0 = g_ecoef[j],     c1 = g_ecoef[j + 1];
            float c2 = g_ecoef[j + 2], c3 = g_ecoef[j + 3];
            const float4* h0 = (const float4*)(h + (size_t)s0 * HID);
            const float4* h1 = (const float4*)(h + (size_t)s1 * HID);
            const float4* h2 = (const float4*)(h + (size_t)s2 * HID);
            const float4* h3 = (const float4*)(h + (size_t)s3 * HID);
            float4 v00 = h0[lane],      v01 = h0[32 + lane];
            float4 v10 = h1[lane],      v11 = h1[32 + lane];
            float4 v20 = h2[lane],      v21 = h2[32 + lane];
            float4 v30 = h3[lane],      v31 = h3[32 + lane];
            a0 = f4fma(v00, c0, a0); a1 = f4fma(v01, c0, a1);
            a0 = f4fma(v10, c1, a0); a1 = f4fma(v11, c1, a1);
            a0 = f4fma(v20, c2, a0); a1 = f4fma(v21, c2, a1);
            a0 = f4fma(v30, c3, a0); a1 = f4fma(v31, c3, a1);
        }
        for (; j < end; j++) {
            int s  = g_esrc[j];
            float c = g_ecoef[j];
            const float4* hs = (const float4*)(h + (size_t)s * HID);
            a0 = f4fma(hs[lane],      c, a0);
            a1 = f4fma(hs[32 + lane], c, a1);
        }

        float4* ad = (float4*)(agg + (size_t)d * HID);
        ad[lane]      = a0;
        ad[32 + lane] = a1;
        f4acc(cs0, a0); f4accsq(cq0, a0);
        f4acc(cs1, a1); f4accsq(cq1, a1);
    }

    __shared__ float4 rs0[8][32], rq0[8][32], rs1[8][32], rq1[8][32];
    rs0[w][lane] = cs0; rq0[w][lane] = cq0;
    rs1[w][lane] = cs1; rq1[w][lane] = cq1;
    __syncthreads();
    if (w == 0) {
        float4 ts0 = rs0[0][lane], tq0 = rq0[0][lane];
        float4 ts1 = rs1[0][lane], tq1 = rq1[0][lane];
        #pragma unroll
        for (int i = 1; i < 8; i++) {
            f4acc(ts0, rs0[i][lane]); f4acc(tq0, rq0[i][lane]);
            f4acc(ts1, rs1[i][lane]); f4acc(tq1, rq1[i][lane]);
        }
        int c0 = lane * 4, c1 = 128 + lane * 4;
        atomicAdd(&sum[c0+0], ts0.x); atomicAdd(&sum[c0+1], ts0.y);
        atomicAdd(&sum[c0+2], ts0.z); atomicAdd(&sum[c0+3], ts0.w);
        atomicAdd(&sq[c0+0],  tq0.x); atomicAdd(&sq[c0+1],  tq0.y);
        atomicAdd(&sq[c0+2],  tq0.z); atomicAdd(&sq[c0+3],  tq0.w);
        atomicAdd(&sum[c1+0], ts1.x); atomicAdd(&sum[c1+1], ts1.y);
        atomicAdd(&sum[c1+2], ts1.z); atomicAdd(&sum[c1+3], ts1.w);
        atomicAdd(&sq[c1+0],  tq1.x); atomicAdd(&sq[c1+1],  tq1.y);
        atomicAdd(&sq[c1+2],  tq1.z); atomicAdd(&sq[c1+3],  tq1.w);
    }
}

// ---------------- BN coef (1 block) ----------------
__global__ void bn_coef(const float* __restrict__ sum, const float* __restrict__ sq,
                        const float* __restrict__ gamma, const float* __restrict__ beta,
                        float* __restrict__ ga, float* __restrict__ bb, int N) {
    int c = threadIdx.x;
    float invN = 1.0f / (float)N;
    float mu  = sum[c] * invN;
    float var = sq[c] * invN - mu * mu;
    float rs  = rsqrtf(var + BN_EPS);
    float g   = gamma[c] * rs;
    ga[c] = g;
    bb[c] = beta[c] - mu * g;
}

// ---------------- BN apply + ReLU (final output) ----------------
__global__ __launch_bounds__(256) void bn_apply2(float* __restrict__ a,
                                                 const float* __restrict__ ga,
                                                 const float* __restrict__ bb, int N) {
    int i = blockIdx.x * blockDim.x + threadIdx.x;
    int total = N * (HID / 4);
    if (i >= total) return;
    int c4 = i & 63;
    float4 v = ((float4*)a)[i];
    float4 g = ((const float4*)ga)[c4];
    float4 b = ((const float4*)bb)[c4];
    v.x = fmaxf(0.f, fmaf(v.x, g.x, b.x));
    v.y = fmaxf(0.f, fmaf(v.y, g.y, b.y));
    v.z = fmaxf(0.f, fmaf(v.z, g.z, b.z));
    v.w = fmaxf(0.f, fmaf(v.w, g.w, b.w));
    ((float4*)a)[i] = v;
}

// ---------------- launch ----------------
extern "C" void kernel_launch(void* const* d_in, const int* in_sizes, int n_in,
                              void* d_out, int out_size) {
    const float* x   = (const float*)d_in[0];
    const int*   ei  = (const int*)d_in[1];
    const float* W1  = (const float*)d_in[2];
    const float* b1  = (const float*)d_in[3];
    const float* g1  = (const float*)d_in[4];
    const float* be1 = (const float*)d_in[5];
    const float* W2  = (const float*)d_in[6];
    const float* b2  = (const float*)d_in[7];
    const float* g2  = (const float*)d_in[8];
    const float* be2 = (const float*)d_in[9];
    float* out = (float*)d_out;

    const int IN_DIM = IN_DIM_C;
    int N = in_sizes[0] / IN_DIM;
    int E = in_sizes[1] / 2;
    const int* src = ei;
    const int* dst = ei + E;

    float *hP, *aP, *statsP, *coefP;
    cudaGetSymbolAddress((void**)&hP, g_h);
    cudaGetSymbolAddress((void**)&aP, g_a);
    cudaGetSymbolAddress((void**)&statsP, g_stats);
    cudaGetSymbolAddress((void**)&coefP, g_coef);
    __nv_bfloat16 *w1h, *w1l, *w2h, *w2l, *ahP, *alP;
    cudaGetSymbolAddress((void**)&w1h, g_W1h);
    cudaGetSymbolAddress((void**)&w1l, g_W1l);
    cudaGetSymbolAddress((void**)&w2h, g_W2h);
    cudaGetSymbolAddress((void**)&w2l, g_W2l);
    cudaGetSymbolAddress((void**)&ahP, g_Ah);
    cudaGetSymbolAddress((void**)&alP, g_Al);

    int nb256 = (N + 255) / 256;
    int aggBlocks  = 592;
    int outBlocks  = (N * (HID / 4) + 255) / 256;
    dim3 gemmGrid((N + TBM - 1) / TBM, HID / TBN);
    int cv1 = N * (IN_DIM / 4);
    int cv2 = N * (HID / 4);

    // graph structure + CSR + weight split
    zero_kernel<<<nb256, 256>>>(N);
    deg_count<<<(E + 255) / 256, 256>>>(dst, E);
    wsplit<<<(IN_DIM * HID + 255) / 256, 256>>>(W1, W2);
    scan1<<<nb256, 256>>>(N);
    scan2<<<1, 512>>>(nb256);
    scan3<<<(N + 256) / 256, 256>>>(N, E);
    csr_fill<<<(E + 255) / 256, 256>>>(src, dst, E);

    // ---- layer 1 ----
    convertA<false><<<(cv1 + 255) / 256, 256>>>(x, nullptr, nullptr, cv1, IN_DIM / 4);
    mma_gemm<<<gemmGrid, 256>>>(ahP, alP, w1h, w1l, hP, N, IN_DIM);
    aggregate<<<aggBlocks, 256>>>(hP, b1, aP, statsP + 0, statsP + HID, N);
    bn_coef<<<1, 256>>>(statsP + 0, statsP + HID, g1, be1, coefP + 0, coefP + HID, N);

    // ---- layer 2 (BN1+ReLU fused into convert) ----
    convertA<true><<<(cv2 + 255) / 256, 256>>>(aP, coefP + 0, coefP + HID, cv2, HID / 4);
    mma_gemm<<<gemmGrid, 256>>>(ahP, alP, w2h, w2l, hP, N, HID);
    aggregate<<<aggBlocks, 256>>>(hP, b2, out, statsP + 2 * HID, statsP + 3 * HID, N);
    bn_coef<<<1, 256>>>(statsP + 2 * HID, statsP + 3 * HID, g2, be2,
                        coefP + 2 * HID, coefP + 3 * HID, N);
    bn_apply2<<<outBlocks, 256>>>(out, coefP + 2 * HID, coefP + 3 * HID, N);
}

// round 9
// speedup vs baseline: 1.1279x; 1.1279x over previous
#include <cuda_runtime.h>
#include <cuda_bf16.h>
#include <cuda_fp16.h>
#include <math.h>
#include <stdint.h>

// GNNEncoder: N=100000 nodes, E=800000 edges, 384 -> 256 -> 256
#define MAXN 100000
#define MAXE 800000
#define HID  256
#define IN_DIM_C 384
#define BN_EPS 1e-5f

// ---------------- device scratch ----------------
__device__ float g_h[(size_t)MAXN * HID];
__device__ float g_a[(size_t)MAXN * HID];
__device__ int   g_deg[MAXN];
__device__ int   g_fill[MAXN];
__device__ int   g_rowp[MAXN + 1];
__device__ int   g_blksum[512];
__device__ int   g_blkoff[512];
__device__ int   g_esrc[MAXE];
__device__ float g_ecoef[MAXE];
__device__ float g_dinv[MAXN];
__device__ float g_invdeg[MAXN];
__device__ float g_stats[4 * HID];   // sum1, sq1, sum2, sq2
__device__ float g_coef[4 * HID];    // ga1, bb1, ga2, bb2
// fp16 weights (single, round-to-nearest), layout [K][N]
__device__ __half g_W1f[IN_DIM_C * HID];
__device__ __half g_W2f[HID * HID];
// fp16 split activations (hi/lo), layout [M][K]
__device__ __half g_Ah[(size_t)MAXN * IN_DIM_C];
__device__ __half g_Al[(size_t)MAXN * IN_DIM_C];

// ---------------- float4 helpers ----------------
__device__ __forceinline__ float4 f4fma(float4 a, float s, float4 b) {
    b.x = fmaf(a.x, s, b.x); b.y = fmaf(a.y, s, b.y);
    b.z = fmaf(a.z, s, b.z); b.w = fmaf(a.w, s, b.w);
    return b;
}
__device__ __forceinline__ void f4acc(float4& d, float4 v) {
    d.x += v.x; d.y += v.y; d.z += v.z; d.w += v.w;
}
__device__ __forceinline__ void f4accsq(float4& d, float4 v) {
    d.x = fmaf(v.x, v.x, d.x); d.y = fmaf(v.y, v.y, d.y);
    d.z = fmaf(v.z, v.z, d.z); d.w = fmaf(v.w, v.w, d.w);
}

// ---------------- init / degree ----------------
__global__ void zero_kernel(int N) {
    int i = blockIdx.x * blockDim.x + threadIdx.x;
    if (i < N) { g_deg[i] = 0; g_fill[i] = 0; }
    if (i < 4 * HID) g_stats[i] = 0.0f;
}

__global__ void deg_count(const int* __restrict__ dst, int E) {
    int i = blockIdx.x * blockDim.x + threadIdx.x;
    if (i < E) atomicAdd(&g_deg[dst[i]], 1);
}

// ---------------- weight fp16 round ----------------
__global__ void wsplit(const float* __restrict__ W1, const float* __restrict__ W2) {
    int i = blockIdx.x * blockDim.x + threadIdx.x;
    if (i < IN_DIM_C * HID) g_W1f[i] = __float2half_rn(W1[i]);
    if (i < HID * HID)      g_W2f[i] = __float2half_rn(W2[i]);
}

// ---------------- activation fp16 split (optionally fused BN+ReLU) ----------------
template<bool BNA>
__global__ __launch_bounds__(256) void convertA(const float* __restrict__ src,
                                                const float* __restrict__ ga,
                                                const float* __restrict__ bb,
                                                int total4, int kq) {   // kq = K/4
    int i = blockIdx.x * blockDim.x + threadIdx.x;
    if (i >= total4) return;
    float4 v = ((const float4*)src)[i];
    if (BNA) {
        int c4 = i % kq;
        float4 g = ((const float4*)ga)[c4];
        float4 b = ((const float4*)bb)[c4];
        v.x = fmaxf(0.f, fmaf(v.x, g.x, b.x));
        v.y = fmaxf(0.f, fmaf(v.y, g.y, b.y));
        v.z = fmaxf(0.f, fmaf(v.z, g.z, b.z));
        v.w = fmaxf(0.f, fmaf(v.w, g.w, b.w));
    }
    __half hx = __float2half_rn(v.x);
    __half hy = __float2half_rn(v.y);
    __half hz = __float2half_rn(v.z);
    __half hw = __float2half_rn(v.w);
    __half2 h01 = __halves2half2(hx, hy);
    __half2 h23 = __halves2half2(hz, hw);
    __half2 l01 = __halves2half2(__float2half_rn(v.x - __half2float(hx)),
                                 __float2half_rn(v.y - __half2float(hy)));
    __half2 l23 = __halves2half2(__float2half_rn(v.z - __half2float(hz)),
                                 __float2half_rn(v.w - __half2float(hw)));
    uint2 hp, lp;
    hp.x = *(uint32_t*)&h01; hp.y = *(uint32_t*)&h23;
    lp.x = *(uint32_t*)&l01; lp.y = *(uint32_t*)&l23;
    ((uint2*)g_Ah)[i] = hp;
    ((uint2*)g_Al)[i] = lp;
}

// ---------------- scan of g_deg -> g_rowp + dinv/invdeg (fused) ----------------
__global__ void scan1(int N) {
    __shared__ int s[256];
    int t = threadIdx.x;
    int i = blockIdx.x * 256 + t;
    int v = (i < N) ? g_deg[i] : 0;
    if (i < N) {
        float dg = (float)v + 1.0f;
        g_dinv[i]   = rsqrtf(dg);
        g_invdeg[i] = 1.0f / dg;
    }
    s[t] = v; __syncthreads();
    #pragma unroll
    for (int off = 1; off < 256; off <<= 1) {
        int x = (t >= off) ? s[t - off] : 0;
        __syncthreads();
        s[t] += x;
        __syncthreads();
    }
    if (i < N) g_rowp[i] = s[t] - v;             // exclusive
    if (t == 255) g_blksum[blockIdx.x] = s[t];
}
__global__ void scan2(int nb) {
    __shared__ int s[512];
    int t = threadIdx.x;
    int v = (t < nb) ? g_blksum[t] : 0;
    s[t] = v; __syncthreads();
    #pragma unroll
    for (int off = 1; off < 512; off <<= 1) {
        int x = (t >= off) ? s[t - off] : 0;
        __syncthreads();
        s[t] += x;
        __syncthreads();
    }
    g_blkoff[t] = s[t] - v;
}
__global__ void scan3(int N, int E) {
    int i = blockIdx.x * 256 + threadIdx.x;
    if (i < N) g_rowp[i] += g_blkoff[i >> 8];
    if (i == 0) g_rowp[N] = E;
}

// ---------------- CSR fill ----------------
__global__ void csr_fill(const int* __restrict__ src, const int* __restrict__ dst, int E) {
    int e = blockIdx.x * blockDim.x + threadIdx.x;
    if (e >= E) return;
    int s = src[e], d = dst[e];
    int pos = g_rowp[d] + atomicAdd(&g_fill[d], 1);
    g_esrc[pos]  = s;
    g_ecoef[pos] = g_dinv[s] * g_dinv[d];
}

// ---------------- tensor-core GEMM (fp16 hi/lo A x fp16 B, 2 MMAs, cp.async) ---------
#define TBM 128
#define TBN 128
#define TBK 32
#define APAD 40      // row = 80B
#define BPAD 136     // row = 272B

#define LDSM4(R, addr) \
    asm volatile("ldmatrix.sync.aligned.m8n8.x4.shared.b16 {%0,%1,%2,%3}, [%4];" \
        : "=r"((R)[0]), "=r"((R)[1]), "=r"((R)[2]), "=r"((R)[3]) : "r"(addr))
#define LDSM4T(R, addr) \
    asm volatile("ldmatrix.sync.aligned.m8n8.x4.trans.shared.b16 {%0,%1,%2,%3}, [%4];" \
        : "=r"((R)[0]), "=r"((R)[1]), "=r"((R)[2]), "=r"((R)[3]) : "r"(addr))
#define MMA16816F(d, a, b0, b1) \
    asm volatile("mma.sync.aligned.m16n8k16.row.col.f32.f16.f16.f32 " \
        "{%0,%1,%2,%3},{%4,%5,%6,%7},{%8,%9},{%0,%1,%2,%3};" \
        : "+f"((d)[0]), "+f"((d)[1]), "+f"((d)[2]), "+f"((d)[3]) \
        : "r"((a)[0]), "r"((a)[1]), "r"((a)[2]), "r"((a)[3]), "r"(b0), "r"(b1))
#define CPASYNC16(dst, src, sz) \
    asm volatile("cp.async.cg.shared.global [%0], [%1], 16, %2;" \
        :: "r"(dst), "l"(src), "r"(sz) : "memory")

__global__ __launch_bounds__(256, 2) void mma_gemm(
    const __half* __restrict__ Ah, const __half* __restrict__ Al,
    const __half* __restrict__ Bf,
    float* __restrict__ C, int M, int K)
{
    __shared__ __half sAh[2][TBM][APAD];
    __shared__ __half sAl[2][TBM][APAD];
    __shared__ __half sB [2][TBK][BPAD];

    int tid = threadIdx.x;
    int warp = tid >> 5, lane = tid & 31;
    int wm = warp >> 2, wn = warp & 3;           // 2x4 warp grid, warp tile m64 x n32
    int block_row = blockIdx.x * TBM;
    int block_col = blockIdx.y * TBN;

    float acc[4][4][4];
    #pragma unroll
    for (int i = 0; i < 4; i++)
        #pragma unroll
        for (int j = 0; j < 4; j++)
            #pragma unroll
            for (int k = 0; k < 4; k++) acc[i][j][k] = 0.0f;

    auto issueStage = [&](int st, int k0) {
        // A tiles: 128 rows x 32 fp16 (64B) -> 4 granules/row, 512 granules each (hi+lo)
        #pragma unroll
        for (int q = 0; q < 2; q++) {
            int g = tid * 2 + q;
            int row = g >> 2, c16 = g & 3;
            int grow = block_row + row;
            int sz = (grow < M) ? 16 : 0;
            const __half* ph = Ah + (size_t)grow * K + k0 + c16 * 8;
            const __half* pl = Al + (size_t)grow * K + k0 + c16 * 8;
            uint32_t dh = (uint32_t)__cvta_generic_to_shared(&sAh[st][row][c16 * 8]);
            uint32_t dl = (uint32_t)__cvta_generic_to_shared(&sAl[st][row][c16 * 8]);
            CPASYNC16(dh, ph, sz);
            CPASYNC16(dl, pl, sz);
        }
        // B tile: 32 rows x 128 fp16 (256B) -> 16 granules/row, 512 granules
        #pragma unroll
        for (int q = 0; q < 2; q++) {
            int g = tid * 2 + q;
            int row = g >> 4, c16 = g & 15;
            const __half* pb = Bf + (size_t)(k0 + row) * HID + block_col + c16 * 8;
            uint32_t db = (uint32_t)__cvta_generic_to_shared(&sB[st][row][c16 * 8]);
            CPASYNC16(db, pb, 16);
        }
        asm volatile("cp.async.commit_group;" ::: "memory");
    };

    auto mmaStage = [&](int st) {
        #pragma unroll
        for (int ks = 0; ks < 2; ks++) {
            uint32_t afh[4][4], afl[4][4], bf[2][4];
            #pragma unroll
            for (int mi = 0; mi < 4; mi++) {
                int r = wm * 64 + mi * 16 + (lane & 15);
                int c = ks * 16 + (lane >> 4) * 8;
                uint32_t ah = (uint32_t)__cvta_generic_to_shared(&sAh[st][r][c]);
                uint32_t al = (uint32_t)__cvta_generic_to_shared(&sAl[st][r][c]);
                LDSM4(afh[mi], ah);
                LDSM4(afl[mi], al);
            }
            #pragma unroll
            for (int ni = 0; ni < 2; ni++) {
                int r = ks * 16 + (lane & 15);
                int c = wn * 32 + ni * 16 + (lane >> 4) * 8;
                uint32_t bb = (uint32_t)__cvta_generic_to_shared(&sB[st][r][c]);
                LDSM4T(bf[ni], bb);
            }
            #pragma unroll
            for (int mi = 0; mi < 4; mi++)
                #pragma unroll
                for (int n8 = 0; n8 < 4; n8++) {
                    uint32_t b0 = bf[n8 >> 1][(n8 & 1) * 2];
                    uint32_t b1 = bf[n8 >> 1][(n8 & 1) * 2 + 1];
                    MMA16816F(acc[mi][n8], afh[mi], b0, b1);
                    MMA16816F(acc[mi][n8], afl[mi], b0, b1);
                }
        }
    };

    int nIters = K / TBK;
    issueStage(0, 0);
    for (int it = 0; it < nIters; it++) {
        int cur = it & 1;
        bool more = (it + 1 < nIters);
        if (more) {
            issueStage(cur ^ 1, (it + 1) * TBK);
            asm volatile("cp.async.wait_group 1;" ::: "memory");
        } else {
            asm volatile("cp.async.wait_group 0;" ::: "memory");
        }
        __syncthreads();
        mmaStage(cur);
        __syncthreads();
    }

    #pragma unroll
    for (int mi = 0; mi < 4; mi++) {
        #pragma unroll
        for (int n8 = 0; n8 < 4; n8++) {
            int col = block_col + wn * 32 + n8 * 8 + (lane & 3) * 2;
            #pragma unroll
            for (int h = 0; h < 2; h++) {
                int row = block_row + wm * 64 + mi * 16 + (lane >> 2) + h * 8;
                if (row < M) {
                    *(float2*)(C + (size_t)row * HID + col) =
                        make_float2(acc[mi][n8][h * 2], acc[mi][n8][h * 2 + 1]);
                }
            }
        }
    }
}

// ---------------- pull aggregation + fused BN stats (unroll-4, MLP=8) ----------------
__global__ __launch_bounds__(256) void aggregate(
    const float* __restrict__ h, const float* __restrict__ bias,
    float* __restrict__ agg, float* __restrict__ sum, float* __restrict__ sq, int N)
{
    int lane = threadIdx.x & 31;
    int w    = threadIdx.x >> 5;
    int wId  = (blockIdx.x << 3) + w;
    int nW   = gridDim.x << 3;

    float4 bv0 = ((const float4*)bias)[lane];
    float4 bv1 = ((const float4*)bias)[32 + lane];
    float4 cs0 = make_float4(0,0,0,0), cq0 = make_float4(0,0,0,0);
    float4 cs1 = make_float4(0,0,0,0), cq1 = make_float4(0,0,0,0);

    for (int d = wId; d < N; d += nW) {
        int beg = g_rowp[d], end = g_rowp[d + 1];
        float id = g_invdeg[d];
        const float4* hd = (const float4*)(h + (size_t)d * HID);
        float4 a0 = f4fma(hd[lane],      id, bv0);
        float4 a1 = f4fma(hd[32 + lane], id, bv1);

        int j = beg;
        for (; j + 4 <= end; j += 4) {
            int   s0 = g_esrc[j],     s1 = g_esrc[j + 1];
            int   s2 = g_esrc[j + 2], s3 = g_esrc[j + 3];
            float c0 = g_ecoef[j],     c1 = g_ecoef[j + 1];
            float c2 = g_ecoef[j + 2], c3 = g_ecoef[j + 3];
            const float4* h0 = (const float4*)(h + (size_t)s0 * HID);
            const float4* h1 = (const float4*)(h + (size_t)s1 * HID);
            const float4* h2 = (const float4*)(h + (size_t)s2 * HID);
            const float4* h3 = (const float4*)(h + (size_t)s3 * HID);
            float4 v00 = h0[lane],      v01 = h0[32 + lane];
            float4 v10 = h1[lane],      v11 = h1[32 + lane];
            float4 v20 = h2[lane],      v21 = h2[32 + lane];
            float4 v30 = h3[lane],      v31 = h3[32 + lane];
            a0 = f4fma(v00, c0, a0); a1 = f4fma(v01, c0, a1);
            a0 = f4fma(v10, c1, a0); a1 = f4fma(v11, c1, a1);
            a0 = f4fma(v20, c2, a0); a1 = f4fma(v21, c2, a1);
            a0 = f4fma(v30, c3, a0); a1 = f4fma(v31, c3, a1);
        }
        for (; j < end; j++) {
            int s  = g_esrc[j];
            float c = g_ecoef[j];
            const float4* hs = (const float4*)(h + (size_t)s * HID);
            a0 = f4fma(hs[lane],      c, a0);
            a1 = f4fma(hs[32 + lane], c, a1);
        }

        float4* ad = (float4*)(agg + (size_t)d * HID);
        ad[lane]      = a0;
        ad[32 + lane] = a1;
        f4acc(cs0, a0); f4accsq(cq0, a0);
        f4acc(cs1, a1); f4accsq(cq1, a1);
    }

    __shared__ float4 rs0[8][32], rq0[8][32], rs1[8][32], rq1[8][32];
    rs0[w][lane] = cs0; rq0[w][lane] = cq0;
    rs1[w][lane] = cs1; rq1[w][lane] = cq1;
    __syncthreads();
    if (w == 0) {
        float4 ts0 = rs0[0][lane], tq0 = rq0[0][lane];
        float4 ts1 = rs1[0][lane], tq1 = rq1[0][lane];
        #pragma unroll
        for (int i = 1; i < 8; i++) {
            f4acc(ts0, rs0[i][lane]); f4acc(tq0, rq0[i][lane]);
            f4acc(ts1, rs1[i][lane]); f4acc(tq1, rq1[i][lane]);
        }
        int c0 = lane * 4, c1 = 128 + lane * 4;
        atomicAdd(&sum[c0+0], ts0.x); atomicAdd(&sum[c0+1], ts0.y);
        atomicAdd(&sum[c0+2], ts0.z); atomicAdd(&sum[c0+3], ts0.w);
        atomicAdd(&sq[c0+0],  tq0.x); atomicAdd(&sq[c0+1],  tq0.y);
        atomicAdd(&sq[c0+2],  tq0.z); atomicAdd(&sq[c0+3],  tq0.w);
        atomicAdd(&sum[c1+0], ts1.x); atomicAdd(&sum[c1+1], ts1.y);
        atomicAdd(&sum[c1+2], ts1.z); atomicAdd(&sum[c1+3], ts1.w);
        atomicAdd(&sq[c1+0],  tq1.x); atomicAdd(&sq[c1+1],  tq1.y);
        atomicAdd(&sq[c1+2],  tq1.z); atomicAdd(&sq[c1+3],  tq1.w);
    }
}

// ---------------- BN coef (1 block) ----------------
__global__ void bn_coef(const float* __restrict__ sum, const float* __restrict__ sq,
                        const float* __restrict__ gamma, const float* __restrict__ beta,
                        float* __restrict__ ga, float* __restrict__ bb, int N) {
    int c = threadIdx.x;
    float invN = 1.0f / (float)N;
    float mu  = sum[c] * invN;
    float var = sq[c] * invN - mu * mu;
    float rs  = rsqrtf(var + BN_EPS);
    float g   = gamma[c] * rs;
    ga[c] = g;
    bb[c] = beta[c] - mu * g;
}

// ---------------- BN apply + ReLU (final output) ----------------
__global__ __launch_bounds__(256) void bn_apply2(float* __restrict__ a,
                                                 const float* __restrict__ ga,
                                                 const float* __restrict__ bb, int N) {
    int i = blockIdx.x * blockDim.x + threadIdx.x;
    int total = N * (HID / 4);
    if (i >= total) return;
    int c4 = i & 63;
    float4 v = ((float4*)a)[i];
    float4 g = ((const float4*)ga)[c4];
    float4 b = ((const float4*)bb)[c4];
    v.x = fmaxf(0.f, fmaf(v.x, g.x, b.x));
    v.y = fmaxf(0.f, fmaf(v.y, g.y, b.y));
    v.z = fmaxf(0.f, fmaf(v.z, g.z, b.z));
    v.w = fmaxf(0.f, fmaf(v.w, g.w, b.w));
    ((float4*)a)[i] = v;
}

// ---------------- launch ----------------
extern "C" void kernel_launch(void* const* d_in, const int* in_sizes, int n_in,
                              void* d_out, int out_size) {
    const float* x   = (const float*)d_in[0];
    const int*   ei  = (const int*)d_in[1];
    const float* W1  = (const float*)d_in[2];
    const float* b1  = (const float*)d_in[3];
    const float* g1  = (const float*)d_in[4];
    const float* be1 = (const float*)d_in[5];
    const float* W2  = (const float*)d_in[6];
    const float* b2  = (const float*)d_in[7];
    const float* g2  = (const float*)d_in[8];
    const float* be2 = (const float*)d_in[9];
    float* out = (float*)d_out;

    const int IN_DIM = IN_DIM_C;
    int N = in_sizes[0] / IN_DIM;
    int E = in_sizes[1] / 2;
    const int* src = ei;
    const int* dst = ei + E;

    float *hP, *aP, *statsP, *coefP;
    cudaGetSymbolAddress((void**)&hP, g_h);
    cudaGetSymbolAddress((void**)&aP, g_a);
    cudaGetSymbolAddress((void**)&statsP, g_stats);
    cudaGetSymbolAddress((void**)&coefP, g_coef);
    __half *w1f, *w2f, *ahP, *alP;
    cudaGetSymbolAddress((void**)&w1f, g_W1f);
    cudaGetSymbolAddress((void**)&w2f, g_W2f);
    cudaGetSymbolAddress((void**)&ahP, g_Ah);
    cudaGetSymbolAddress((void**)&alP, g_Al);

    int nb256 = (N + 255) / 256;
    int aggBlocks  = 592;
    int outBlocks  = (N * (HID / 4) + 255) / 256;
    dim3 gemmGrid((N + TBM - 1) / TBM, HID / TBN);
    int cv1 = N * (IN_DIM / 4);
    int cv2 = N * (HID / 4);

    // graph structure + CSR + weight rounding
    zero_kernel<<<nb256, 256>>>(N);
    deg_count<<<(E + 255) / 256, 256>>>(dst, E);
    wsplit<<<(IN_DIM * HID + 255) / 256, 256>>>(W1, W2);
    scan1<<<nb256, 256>>>(N);
    scan2<<<1, 512>>>(nb256);
    scan3<<<(N + 256) / 256, 256>>>(N, E);
    csr_fill<<<(E + 255) / 256, 256>>>(src, dst, E);

    // ---- layer 1 ----
    convertA<false><<<(cv1 + 255) / 256, 256>>>(x, nullptr, nullptr, cv1, IN_DIM / 4);
    mma_gemm<<<gemmGrid, 256>>>(ahP, alP, w1f, hP, N, IN_DIM);
    aggregate<<<aggBlocks, 256>>>(hP, b1, aP, statsP + 0, statsP + HID, N);
    bn_coef<<<1, 256>>>(statsP + 0, statsP + HID, g1, be1, coefP + 0, coefP + HID, N);

    // ---- layer 2 (BN1+ReLU fused into convert) ----
    convertA<true><<<(cv2 + 255) / 256, 256>>>(aP, coefP + 0, coefP + HID, cv2, HID / 4);
    mma_gemm<<<gemmGrid, 256>>>(ahP, alP, w2f, hP, N, HID);
    aggregate<<<aggBlocks, 256>>>(hP, b2, out, statsP + 2 * HID, statsP + 3 * HID, N);
    bn_coef<<<1, 256>>>(statsP + 2 * HID, statsP + 3 * HID, g2, be2,
                        coefP + 2 * HID, coefP + 3 * HID, N);
    bn_apply2<<<outBlocks, 256>>>(out, coefP + 2 * HID, coefP + 3 * HID, N);
}

// round 13
// speedup vs baseline: 1.1671x; 1.0348x over previous
#include <cuda_runtime.h>
#include <cuda_bf16.h>
#include <cuda_fp16.h>
#include <math.h>
#include <stdint.h>

// GNNEncoder: N=100000 nodes, E=800000 edges, 384 -> 256 -> 256
#define MAXN 100000
#define MAXE 800000
#define HID  256
#define IN_DIM_C 384
#define BN_EPS 1e-5f

// ---------------- device scratch ----------------
__device__ float g_h[(size_t)MAXN * HID];
__device__ float g_a[(size_t)MAXN * HID];
__device__ int   g_deg[MAXN];
__device__ int   g_fill[MAXN];
__device__ int   g_rowp[MAXN + 1];
__device__ int   g_blksum[512];
__device__ int   g_blkoff[512];
__device__ int   g_esrc[MAXE];
__device__ float g_ecoef[MAXE];
__device__ float g_dinv[MAXN];
__device__ float g_invdeg[MAXN];
__device__ float g_stats[4 * HID];   // sum1, sq1, sum2, sq2
__device__ float g_coef[4 * HID];    // ga1, bb1, ga2, bb2
// fp16 weights (single, round-to-nearest), layout [K][N]
__device__ __half g_W1f[IN_DIM_C * HID];
__device__ __half g_W2f[HID * HID];
// fp16 split activations (hi/lo), layout [M][K]
__device__ __half g_Ah[(size_t)MAXN * IN_DIM_C];
__device__ __half g_Al[(size_t)MAXN * IN_DIM_C];

// ---------------- float4 helpers ----------------
__device__ __forceinline__ float4 f4fma(float4 a, float s, float4 b) {
    b.x = fmaf(a.x, s, b.x); b.y = fmaf(a.y, s, b.y);
    b.z = fmaf(a.z, s, b.z); b.w = fmaf(a.w, s, b.w);
    return b;
}
__device__ __forceinline__ void f4acc(float4& d, float4 v) {
    d.x += v.x; d.y += v.y; d.z += v.z; d.w += v.w;
}
__device__ __forceinline__ void f4accsq(float4& d, float4 v) {
    d.x = fmaf(v.x, v.x, d.x); d.y = fmaf(v.y, v.y, d.y);
    d.z = fmaf(v.z, v.z, d.z); d.w = fmaf(v.w, v.w, d.w);
}

// ---------------- init / degree ----------------
__global__ void zero_kernel(int N) {
    int i = blockIdx.x * blockDim.x + threadIdx.x;
    if (i < N) { g_deg[i] = 0; g_fill[i] = 0; }
    if (i < 4 * HID) g_stats[i] = 0.0f;
}

__global__ void deg_count(const int* __restrict__ dst, int E) {
    int i = blockIdx.x * blockDim.x + threadIdx.x;
    if (i < E) atomicAdd(&g_deg[dst[i]], 1);
}

// ---------------- weight fp16 round ----------------
__global__ void wsplit(const float* __restrict__ W1, const float* __restrict__ W2) {
    int i = blockIdx.x * blockDim.x + threadIdx.x;
    if (i < IN_DIM_C * HID) g_W1f[i] = __float2half_rn(W1[i]);
    if (i < HID * HID)      g_W2f[i] = __float2half_rn(W2[i]);
}

// ---------------- activation fp16 split (optionally fused BN+ReLU) ----------------
template<bool BNA>
__global__ __launch_bounds__(256) void convertA(const float* __restrict__ src,
                                                const float* __restrict__ ga,
                                                const float* __restrict__ bb,
                                                int total4, int kq) {   // kq = K/4
    int i = blockIdx.x * blockDim.x + threadIdx.x;
    if (i >= total4) return;
    float4 v = ((const float4*)src)[i];
    if (BNA) {
        int c4 = i % kq;
        float4 g = ((const float4*)ga)[c4];
        float4 b = ((const float4*)bb)[c4];
        v.x = fmaxf(0.f, fmaf(v.x, g.x, b.x));
        v.y = fmaxf(0.f, fmaf(v.y, g.y, b.y));
        v.z = fmaxf(0.f, fmaf(v.z, g.z, b.z));
        v.w = fmaxf(0.f, fmaf(v.w, g.w, b.w));
    }
    __half hx = __float2half_rn(v.x);
    __half hy = __float2half_rn(v.y);
    __half hz = __float2half_rn(v.z);
    __half hw = __float2half_rn(v.w);
    __half2 h01 = __halves2half2(hx, hy);
    __half2 h23 = __halves2half2(hz, hw);
    __half2 l01 = __halves2half2(__float2half_rn(v.x - __half2float(hx)),
                                 __float2half_rn(v.y - __half2float(hy)));
    __half2 l23 = __halves2half2(__float2half_rn(v.z - __half2float(hz)),
                                 __float2half_rn(v.w - __half2float(hw)));
    uint2 hp, lp;
    hp.x = *(uint32_t*)&h01; hp.y = *(uint32_t*)&h23;
    lp.x = *(uint32_t*)&l01; lp.y = *(uint32_t*)&l23;
    ((uint2*)g_Ah)[i] = hp;
    ((uint2*)g_Al)[i] = lp;
}

// ---------------- scan of g_deg -> g_rowp + dinv/invdeg (fused) ----------------
__global__ void scan1(int N) {
    __shared__ int s[256];
    int t = threadIdx.x;
    int i = blockIdx.x * 256 + t;
    int v = (i < N) ? g_deg[i] : 0;
    if (i < N) {
        float dg = (float)v + 1.0f;
        g_dinv[i]   = rsqrtf(dg);
        g_invdeg[i] = 1.0f / dg;
    }
    s[t] = v; __syncthreads();
    #pragma unroll
    for (int off = 1; off < 256; off <<= 1) {
        int x = (t >= off) ? s[t - off] : 0;
        __syncthreads();
        s[t] += x;
        __syncthreads();
    }
    if (i < N) g_rowp[i] = s[t] - v;             // exclusive
    if (t == 255) g_blksum[blockIdx.x] = s[t];
}
__global__ void scan2(int nb) {
    __shared__ int s[512];
    int t = threadIdx.x;
    int v = (t < nb) ? g_blksum[t] : 0;
    s[t] = v; __syncthreads();
    #pragma unroll
    for (int off = 1; off < 512; off <<= 1) {
        int x = (t >= off) ? s[t - off] : 0;
        __syncthreads();
        s[t] += x;
        __syncthreads();
    }
    g_blkoff[t] = s[t] - v;
}
__global__ void scan3(int N, int E) {
    int i = blockIdx.x * 256 + threadIdx.x;
    if (i < N) g_rowp[i] += g_blkoff[i >> 8];
    if (i == 0) g_rowp[N] = E;
}

// ---------------- CSR fill ----------------
__global__ void csr_fill(const int* __restrict__ src, const int* __restrict__ dst, int E) {
    int e = blockIdx.x * blockDim.x + threadIdx.x;
    if (e >= E) return;
    int s = src[e], d = dst[e];
    int pos = g_rowp[d] + atomicAdd(&g_fill[d], 1);
    g_esrc[pos]  = s;
    g_ecoef[pos] = g_dinv[s] * g_dinv[d];
}

// ---------------- tensor-core GEMM (fp16 hi/lo A x fp16 B, 3-stage cp.async) ---------
#define TBM 128
#define TBN 128
#define TBK 32
#define APAD 40      // row = 80B
#define BPAD 136     // row = 272B

#define LDSM4(R, addr) \
    asm volatile("ldmatrix.sync.aligned.m8n8.x4.shared.b16 {%0,%1,%2,%3}, [%4];" \
        : "=r"((R)[0]), "=r"((R)[1]), "=r"((R)[2]), "=r"((R)[3]) : "r"(addr))
#define LDSM4T(R, addr) \
    asm volatile("ldmatrix.sync.aligned.m8n8.x4.trans.shared.b16 {%0,%1,%2,%3}, [%4];" \
        : "=r"((R)[0]), "=r"((R)[1]), "=r"((R)[2]), "=r"((R)[3]) : "r"(addr))
#define MMA16816F(d, a, b0, b1) \
    asm volatile("mma.sync.aligned.m16n8k16.row.col.f32.f16.f16.f32 " \
        "{%0,%1,%2,%3},{%4,%5,%6,%7},{%8,%9},{%0,%1,%2,%3};" \
        : "+f"((d)[0]), "+f"((d)[1]), "+f"((d)[2]), "+f"((d)[3]) \
        : "r"((a)[0]), "r"((a)[1]), "r"((a)[2]), "r"((a)[3]), "r"(b0), "r"(b1))
#define CPASYNC16(dst, src, sz) \
    asm volatile("cp.async.cg.shared.global [%0], [%1], 16, %2;" \
        :: "r"(dst), "l"(src), "r"(sz) : "memory")
#define CPCOMMIT() asm volatile("cp.async.commit_group;" ::: "memory")

__global__ __launch_bounds__(256, 2) void mma_gemm(
    const __half* __restrict__ Ah, const __half* __restrict__ Al,
    const __half* __restrict__ Bf,
    float* __restrict__ C, int M, int K)
{
    __shared__ __half sAh[3][TBM][APAD];
    __shared__ __half sAl[3][TBM][APAD];
    __shared__ __half sB [3][TBK][BPAD];

    int tid = threadIdx.x;
    int warp = tid >> 5, lane = tid & 31;
    int wm = warp >> 2, wn = warp & 3;           // 2x4 warp grid, warp tile m64 x n32
    int block_row = blockIdx.x * TBM;
    int block_col = blockIdx.y * TBN;

    float acc[4][4][4];
    #pragma unroll
    for (int i = 0; i < 4; i++)
        #pragma unroll
        for (int j = 0; j < 4; j++)
            #pragma unroll
            for (int k = 0; k < 4; k++) acc[i][j][k] = 0.0f;

    auto issueStage = [&](int st, int k0) {
        // A tiles: 128 rows x 32 fp16 (64B) -> 4 granules/row, 512 granules each (hi+lo)
        #pragma unroll
        for (int q = 0; q < 2; q++) {
            int g = tid * 2 + q;
            int row = g >> 2, c16 = g & 3;
            int grow = block_row + row;
            int sz = (grow < M) ? 16 : 0;
            const __half* ph = Ah + (size_t)grow * K + k0 + c16 * 8;
            const __half* pl = Al + (size_t)grow * K + k0 + c16 * 8;
            uint32_t dh = (uint32_t)__cvta_generic_to_shared(&sAh[st][row][c16 * 8]);
            uint32_t dl = (uint32_t)__cvta_generic_to_shared(&sAl[st][row][c16 * 8]);
            CPASYNC16(dh, ph, sz);
            CPASYNC16(dl, pl, sz);
        }
        // B tile: 32 rows x 128 fp16 (256B) -> 16 granules/row, 512 granules
        #pragma unroll
        for (int q = 0; q < 2; q++) {
            int g = tid * 2 + q;
            int row = g >> 4, c16 = g & 15;
            const __half* pb = Bf + (size_t)(k0 + row) * HID + block_col + c16 * 8;
            uint32_t db = (uint32_t)__cvta_generic_to_shared(&sB[st][row][c16 * 8]);
            CPASYNC16(db, pb, 16);
        }
    };

    auto mmaStage = [&](int st) {
        #pragma unroll
        for (int ks = 0; ks < 2; ks++) {
            uint32_t afh[4][4], afl[4][4], bf[2][4];
            #pragma unroll
            for (int mi = 0; mi < 4; mi++) {
                int r = wm * 64 + mi * 16 + (lane & 15);
                int c = ks * 16 + (lane >> 4) * 8;
                uint32_t ah = (uint32_t)__cvta_generic_to_shared(&sAh[st][r][c]);
                uint32_t al = (uint32_t)__cvta_generic_to_shared(&sAl[st][r][c]);
                LDSM4(afh[mi], ah);
                LDSM4(afl[mi], al);
            }
            #pragma unroll
            for (int ni = 0; ni < 2; ni++) {
                int r = ks * 16 + (lane & 15);
                int c = wn * 32 + ni * 16 + (lane >> 4) * 8;
                uint32_t bb = (uint32_t)__cvta_generic_to_shared(&sB[st][r][c]);
                LDSM4T(bf[ni], bb);
            }
            #pragma unroll
            for (int mi = 0; mi < 4; mi++)
                #pragma unroll
                for (int n8 = 0; n8 < 4; n8++) {
                    uint32_t b0 = bf[n8 >> 1][(n8 & 1) * 2];
                    uint32_t b1 = bf[n8 >> 1][(n8 & 1) * 2 + 1];
                    MMA16816F(acc[mi][n8], afh[mi], b0, b1);
                    MMA16816F(acc[mi][n8], afl[mi], b0, b1);
                }
        }
    };

    int nIters = K / TBK;
    issueStage(0, 0);
    CPCOMMIT();
    issueStage(1, TBK);
    CPCOMMIT();

    for (int it = 0; it < nIters; it++) {
        int cur = it % 3;
        asm volatile("cp.async.wait_group 1;" ::: "memory");
        __syncthreads();                 // stage `cur` visible to all; frees stage (it-1)%3
        mmaStage(cur);
        if (it + 2 < nIters) issueStage((it + 2) % 3, (it + 2) * TBK);
        CPCOMMIT();                      // uniform commit keeps wait_group count constant
    }

    #pragma unroll
    for (int mi = 0; mi < 4; mi++) {
        #pragma unroll
        for (int n8 = 0; n8 < 4; n8++) {
            int col = block_col + wn * 32 + n8 * 8 + (lane & 3) * 2;
            #pragma unroll
            for (int h = 0; h < 2; h++) {
                int row = block_row + wm * 64 + mi * 16 + (lane >> 2) + h * 8;
                if (row < M) {
                    *(float2*)(C + (size_t)row * HID + col) =
                        make_float2(acc[mi][n8][h * 2], acc[mi][n8][h * 2 + 1]);
                }
            }
        }
    }
}

// ---------------- pull aggregation + fused BN stats (unroll-4, MLP=8) ----------------
__global__ __launch_bounds__(256) void aggregate(
    const float* __restrict__ h, const float* __restrict__ bias,
    float* __restrict__ agg, float* __restrict__ sum, float* __restrict__ sq, int N)
{
    int lane = threadIdx.x & 31;
    int w    = threadIdx.x >> 5;
    int wId  = (blockIdx.x << 3) + w;
    int nW   = gridDim.x << 3;

    float4 bv0 = ((const float4*)bias)[lane];
    float4 bv1 = ((const float4*)bias)[32 + lane];
    float4 cs0 = make_float4(0,0,0,0), cq0 = make_float4(0,0,0,0);
    float4 cs1 = make_float4(0,0,0,0), cq1 = make_float4(0,0,0,0);

    for (int d = wId; d < N; d += nW) {
        int beg = g_rowp[d], end = g_rowp[d + 1];
        float id = g_invdeg[d];
        const float4* hd = (const float4*)(h + (size_t)d * HID);
        float4 a0 = f4fma(hd[lane],      id, bv0);
        float4 a1 = f4fma(hd[32 + lane], id, bv1);

        int j = beg;
        for (; j + 4 <= end; j += 4) {
            int   s0 = g_esrc[j],     s1 = g_esrc[j + 1];
            int   s2 = g_esrc[j + 2], s3 = g_esrc[j + 3];
            float c0 = g_ecoef[j],     c1 = g_ecoef[j + 1];
            float c2 = g_ecoef[j + 2], c3 = g_ecoef[j + 3];
            const float4* h0 = (const float4*)(h + (size_t)s0 * HID);
            const float4* h1 = (const float4*)(h + (size_t)s1 * HID);
            const float4* h2 = (const float4*)(h + (size_t)s2 * HID);
            const float4* h3 = (const float4*)(h + (size_t)s3 * HID);
            float4 v00 = h0[lane],      v01 = h0[32 + lane];
            float4 v10 = h1[lane],      v11 = h1[32 + lane];
            float4 v20 = h2[lane],      v21 = h2[32 + lane];
            float4 v30 = h3[lane],      v31 = h3[32 + lane];
            a0 = f4fma(v00, c0, a0); a1 = f4fma(v01, c0, a1);
            a0 = f4fma(v10, c1, a0); a1 = f4fma(v11, c1, a1);
            a0 = f4fma(v20, c2, a0); a1 = f4fma(v21, c2, a1);
            a0 = f4fma(v30, c3, a0); a1 = f4fma(v31, c3, a1);
        }
        for (; j < end; j++) {
            int s  = g_esrc[j];
            float c = g_ecoef[j];
            const float4* hs = (const float4*)(h + (size_t)s * HID);
            a0 = f4fma(hs[lane],      c, a0);
            a1 = f4fma(hs[32 + lane], c, a1);
        }

        float4* ad = (float4*)(agg + (size_t)d * HID);
        ad[lane]      = a0;
        ad[32 + lane] = a1;
        f4acc(cs0, a0); f4accsq(cq0, a0);
        f4acc(cs1, a1); f4accsq(cq1, a1);
    }

    __shared__ float4 rs0[8][32], rq0[8][32], rs1[8][32], rq1[8][32];
    rs0[w][lane] = cs0; rq0[w][lane] = cq0;
    rs1[w][lane] = cs1; rq1[w][lane] = cq1;
    __syncthreads();
    if (w == 0) {
        float4 ts0 = rs0[0][lane], tq0 = rq0[0][lane];
        float4 ts1 = rs1[0][lane], tq1 = rq1[0][lane];
        #pragma unroll
        for (int i = 1; i < 8; i++) {
            f4acc(ts0, rs0[i][lane]); f4acc(tq0, rq0[i][lane]);
            f4acc(ts1, rs1[i][lane]); f4acc(tq1, rq1[i][lane]);
        }
        int c0 = lane * 4, c1 = 128 + lane * 4;
        atomicAdd(&sum[c0+0], ts0.x); atomicAdd(&sum[c0+1], ts0.y);
        atomicAdd(&sum[c0+2], ts0.z); atomicAdd(&sum[c0+3], ts0.w);
        atomicAdd(&sq[c0+0],  tq0.x); atomicAdd(&sq[c0+1],  tq0.y);
        atomicAdd(&sq[c0+2],  tq0.z); atomicAdd(&sq[c0+3],  tq0.w);
        atomicAdd(&sum[c1+0], ts1.x); atomicAdd(&sum[c1+1], ts1.y);
        atomicAdd(&sum[c1+2], ts1.z); atomicAdd(&sum[c1+3], ts1.w);
        atomicAdd(&sq[c1+0],  tq1.x); atomicAdd(&sq[c1+1],  tq1.y);
        atomicAdd(&sq[c1+2],  tq1.z); atomicAdd(&sq[c1+3],  tq1.w);
    }
}

// ---------------- BN coef (1 block) ----------------
__global__ void bn_coef(const float* __restrict__ sum, const float* __restrict__ sq,
                        const float* __restrict__ gamma, const float* __restrict__ beta,
                        float* __restrict__ ga, float* __restrict__ bb, int N) {
    int c = threadIdx.x;
    float invN = 1.0f / (float)N;
    float mu  = sum[c] * invN;
    float var = sq[c] * invN - mu * mu;
    float rs  = rsqrtf(var + BN_EPS);
    float g   = gamma[c] * rs;
    ga[c] = g;
    bb[c] = beta[c] - mu * g;
}

// ---------------- BN apply + ReLU (final output) ----------------
__global__ __launch_bounds__(256) void bn_apply2(float* __restrict__ a,
                                                 const float* __restrict__ ga,
                                                 const float* __restrict__ bb, int N) {
    int i = blockIdx.x * blockDim.x + threadIdx.x;
    int total = N * (HID / 4);
    if (i >= total) return;
    int c4 = i & 63;
    float4 v = ((float4*)a)[i];
    float4 g = ((const float4*)ga)[c4];
    float4 b = ((const float4*)bb)[c4];
    v.x = fmaxf(0.f, fmaf(v.x, g.x, b.x));
    v.y = fmaxf(0.f, fmaf(v.y, g.y, b.y));
    v.z = fmaxf(0.f, fmaf(v.z, g.z, b.z));
    v.w = fmaxf(0.f, fmaf(v.w, g.w, b.w));
    ((float4*)a)[i] = v;
}

// ---------------- launch ----------------
extern "C" void kernel_launch(void* const* d_in, const int* in_sizes, int n_in,
                              void* d_out, int out_size) {
    const float* x   = (const float*)d_in[0];
    const int*   ei  = (const int*)d_in[1];
    const float* W1  = (const float*)d_in[2];
    const float* b1  = (const float*)d_in[3];
    const float* g1  = (const float*)d_in[4];
    const float* be1 = (const float*)d_in[5];
    const float* W2  = (const float*)d_in[6];
    const float* b2  = (const float*)d_in[7];
    const float* g2  = (const float*)d_in[8];
    const float* be2 = (const float*)d_in[9];
    float* out = (float*)d_out;

    const int IN_DIM = IN_DIM_C;
    int N = in_sizes[0] / IN_DIM;
    int E = in_sizes[1] / 2;
    const int* src = ei;
    const int* dst = ei + E;

    float *hP, *aP, *statsP, *coefP;
    cudaGetSymbolAddress((void**)&hP, g_h);
    cudaGetSymbolAddress((void**)&aP, g_a);
    cudaGetSymbolAddress((void**)&statsP, g_stats);
    cudaGetSymbolAddress((void**)&coefP, g_coef);
    __half *w1f, *w2f, *ahP, *alP;
    cudaGetSymbolAddress((void**)&w1f, g_W1f);
    cudaGetSymbolAddress((void**)&w2f, g_W2f);
    cudaGetSymbolAddress((void**)&ahP, g_Ah);
    cudaGetSymbolAddress((void**)&alP, g_Al);

    int nb256 = (N + 255) / 256;
    int aggBlocks  = 592;
    int outBlocks  = (N * (HID / 4) + 255) / 256;
    dim3 gemmGrid((N + TBM - 1) / TBM, HID / TBN);
    int cv1 = N * (IN_DIM / 4);
    int cv2 = N * (HID / 4);

    // graph structure + CSR + weight rounding
    zero_kernel<<<nb256, 256>>>(N);
    deg_count<<<(E + 255) / 256, 256>>>(dst, E);
    wsplit<<<(IN_DIM * HID + 255) / 256, 256>>>(W1, W2);
    scan1<<<nb256, 256>>>(N);
    scan2<<<1, 512>>>(nb256);
    scan3<<<(N + 256) / 256, 256>>>(N, E);
    csr_fill<<<(E + 255) / 256, 256>>>(src, dst, E);

    // ---- layer 1 ----
    convertA<false><<<(cv1 + 255) / 256, 256>>>(x, nullptr, nullptr, cv1, IN_DIM / 4);
    mma_gemm<<<gemmGrid, 256>>>(ahP, alP, w1f, hP, N, IN_DIM);
    aggregate<<<aggBlocks, 256>>>(hP, b1, aP, statsP + 0, statsP + HID, N);
    bn_coef<<<1, 256>>>(statsP + 0, statsP + HID, g1, be1, coefP + 0, coefP + HID, N);

    // ---- layer 2 (BN1+ReLU fused into convert) ----
    convertA<true><<<(cv2 + 255) / 256, 256>>>(aP, coefP + 0, coefP + HID, cv2, HID / 4);
    mma_gemm<<<gemmGrid, 256>>>(ahP, alP, w2f, hP, N, HID);
    aggregate<<<aggBlocks, 256>>>(hP, b2, out, statsP + 2 * HID, statsP + 3 * HID, N);
    bn_coef<<<1, 256>>>(statsP + 2 * HID, statsP + 3 * HID, g2, be2,
                        coefP + 2 * HID, coefP + 3 * HID, N);
    bn_apply2<<<outBlocks, 256>>>(out, coefP + 2 * HID, coefP + 3 * HID, N);
}

// round 14
// speedup vs baseline: 1.1925x; 1.0218x over previous
#include <cuda_runtime.h>
#include <cuda_bf16.h>
#include <cuda_fp16.h>
#include <math.h>
#include <stdint.h>

// GNNEncoder: N=100000 nodes, E=800000 edges, 384 -> 256 -> 256
#define MAXN 100000
#define MAXE 800000
#define HID  256
#define IN_DIM_C 384
#define BN_EPS 1e-5f

// ---------------- device scratch ----------------
__device__ __half g_hH[(size_t)MAXN * HID];    // GEMM output, fp16 (gather-optimized)
__device__ float g_a[(size_t)MAXN * HID];
__device__ int   g_deg[MAXN];
__device__ int   g_fill[MAXN];
__device__ int   g_rowp[MAXN + 1];
__device__ int   g_blksum[512];
__device__ int   g_blkoff[512];
__device__ int   g_esrc[MAXE];
__device__ float g_ecoef[MAXE];
__device__ float g_dinv[MAXN];
__device__ float g_invdeg[MAXN];
__device__ float g_stats[4 * HID];   // sum1, sq1, sum2, sq2
__device__ float g_coef[4 * HID];    // ga1, bb1, ga2, bb2
// fp16 weights (round-to-nearest), layout [K][N]
__device__ __half g_W1f[IN_DIM_C * HID];
__device__ __half g_W2f[HID * HID];
// fp16 split activations (hi/lo), layout [M][K]
__device__ __half g_Ah[(size_t)MAXN * IN_DIM_C];
__device__ __half g_Al[(size_t)MAXN * IN_DIM_C];

// ---------------- helpers ----------------
__device__ __forceinline__ void f4acc(float4& d, float4 v) {
    d.x += v.x; d.y += v.y; d.z += v.z; d.w += v.w;
}
__device__ __forceinline__ void f4accsq(float4& d, float4 v) {
    d.x = fmaf(v.x, v.x, d.x); d.y = fmaf(v.y, v.y, d.y);
    d.z = fmaf(v.z, v.z, d.z); d.w = fmaf(v.w, v.w, d.w);
}
// 8 halves (uint4) -> two float4
__device__ __forceinline__ void h8tof8(uint4 v, float4& f0, float4& f1) {
    __half2* p = (__half2*)&v;
    float2 x0 = __half22float2(p[0]);
    float2 x1 = __half22float2(p[1]);
    float2 x2 = __half22float2(p[2]);
    float2 x3 = __half22float2(p[3]);
    f0 = make_float4(x0.x, x0.y, x1.x, x1.y);
    f1 = make_float4(x2.x, x2.y, x3.x, x3.y);
}
__device__ __forceinline__ void fma8(uint4 v, float c, float4& a0, float4& a1) {
    float4 f0, f1;
    h8tof8(v, f0, f1);
    a0.x = fmaf(f0.x, c, a0.x); a0.y = fmaf(f0.y, c, a0.y);
    a0.z = fmaf(f0.z, c, a0.z); a0.w = fmaf(f0.w, c, a0.w);
    a1.x = fmaf(f1.x, c, a1.x); a1.y = fmaf(f1.y, c, a1.y);
    a1.z = fmaf(f1.z, c, a1.z); a1.w = fmaf(f1.w, c, a1.w);
}

// ---------------- init / degree ----------------
__global__ void zero_kernel(int N) {
    int i = blockIdx.x * blockDim.x + threadIdx.x;
    if (i < N) { g_deg[i] = 0; g_fill[i] = 0; }
    if (i < 4 * HID) g_stats[i] = 0.0f;
}

__global__ void deg_count(const int* __restrict__ dst, int E) {
    int i = blockIdx.x * blockDim.x + threadIdx.x;
    if (i < E) atomicAdd(&g_deg[dst[i]], 1);
}

// ---------------- weight fp16 round ----------------
__global__ void wsplit(const float* __restrict__ W1, const float* __restrict__ W2) {
    int i = blockIdx.x * blockDim.x + threadIdx.x;
    if (i < IN_DIM_C * HID) g_W1f[i] = __float2half_rn(W1[i]);
    if (i < HID * HID)      g_W2f[i] = __float2half_rn(W2[i]);
}

// ---------------- activation fp16 split (optionally fused BN+ReLU) ----------------
template<bool BNA>
__global__ __launch_bounds__(256) void convertA(const float* __restrict__ src,
                                                const float* __restrict__ ga,
                                                const float* __restrict__ bb,
                                                int total4, int kq) {   // kq = K/4
    int i = blockIdx.x * blockDim.x + threadIdx.x;
    if (i >= total4) return;
    float4 v = ((const float4*)src)[i];
    if (BNA) {
        int c4 = i % kq;
        float4 g = ((const float4*)ga)[c4];
        float4 b = ((const float4*)bb)[c4];
        v.x = fmaxf(0.f, fmaf(v.x, g.x, b.x));
        v.y = fmaxf(0.f, fmaf(v.y, g.y, b.y));
        v.z = fmaxf(0.f, fmaf(v.z, g.z, b.z));
        v.w = fmaxf(0.f, fmaf(v.w, g.w, b.w));
    }
    __half hx = __float2half_rn(v.x);
    __half hy = __float2half_rn(v.y);
    __half hz = __float2half_rn(v.z);
    __half hw = __float2half_rn(v.w);
    __half2 h01 = __halves2half2(hx, hy);
    __half2 h23 = __halves2half2(hz, hw);
    __half2 l01 = __halves2half2(__float2half_rn(v.x - __half2float(hx)),
                                 __float2half_rn(v.y - __half2float(hy)));
    __half2 l23 = __halves2half2(__float2half_rn(v.z - __half2float(hz)),
                                 __float2half_rn(v.w - __half2float(hw)));
    uint2 hp, lp;
    hp.x = *(uint32_t*)&h01; hp.y = *(uint32_t*)&h23;
    lp.x = *(uint32_t*)&l01; lp.y = *(uint32_t*)&l23;
    ((uint2*)g_Ah)[i] = hp;
    ((uint2*)g_Al)[i] = lp;
}

// ---------------- scan of g_deg -> g_rowp + dinv/invdeg (fused) ----------------
__global__ void scan1(int N) {
    __shared__ int s[256];
    int t = threadIdx.x;
    int i = blockIdx.x * 256 + t;
    int v = (i < N) ? g_deg[i] : 0;
    if (i < N) {
        float dg = (float)v + 1.0f;
        g_dinv[i]   = rsqrtf(dg);
        g_invdeg[i] = 1.0f / dg;
    }
    s[t] = v; __syncthreads();
    #pragma unroll
    for (int off = 1; off < 256; off <<= 1) {
        int x = (t >= off) ? s[t - off] : 0;
        __syncthreads();
        s[t] += x;
        __syncthreads();
    }
    if (i < N) g_rowp[i] = s[t] - v;             // exclusive
    if (t == 255) g_blksum[blockIdx.x] = s[t];
}
__global__ void scan2(int nb) {
    __shared__ int s[512];
    int t = threadIdx.x;
    int v = (t < nb) ? g_blksum[t] : 0;
    s[t] = v; __syncthreads();
    #pragma unroll
    for (int off = 1; off < 512; off <<= 1) {
        int x = (t >= off) ? s[t - off] : 0;
        __syncthreads();
        s[t] += x;
        __syncthreads();
    }
    g_blkoff[t] = s[t] - v;
}
__global__ void scan3(int N, int E) {
    int i = blockIdx.x * 256 + threadIdx.x;
    if (i < N) g_rowp[i] += g_blkoff[i >> 8];
    if (i == 0) g_rowp[N] = E;
}

// ---------------- CSR fill ----------------
__global__ void csr_fill(const int* __restrict__ src, const int* __restrict__ dst, int E) {
    int e = blockIdx.x * blockDim.x + threadIdx.x;
    if (e >= E) return;
    int s = src[e], d = dst[e];
    int pos = g_rowp[d] + atomicAdd(&g_fill[d], 1);
    g_esrc[pos]  = s;
    g_ecoef[pos] = g_dinv[s] * g_dinv[d];
}

// ---------------- tensor-core GEMM (fp16 hi/lo A x fp16 B, 3-stage cp.async) ---------
#define TBM 128
#define TBN 128
#define TBK 32
#define APAD 40      // row = 80B
#define BPAD 136     // row = 272B

#define LDSM4(R, addr) \
    asm volatile("ldmatrix.sync.aligned.m8n8.x4.shared.b16 {%0,%1,%2,%3}, [%4];" \
        : "=r"((R)[0]), "=r"((R)[1]), "=r"((R)[2]), "=r"((R)[3]) : "r"(addr))
#define LDSM4T(R, addr) \
    asm volatile("ldmatrix.sync.aligned.m8n8.x4.trans.shared.b16 {%0,%1,%2,%3}, [%4];" \
        : "=r"((R)[0]), "=r"((R)[1]), "=r"((R)[2]), "=r"((R)[3]) : "r"(addr))
#define MMA16816F(d, a, b0, b1) \
    asm volatile("mma.sync.aligned.m16n8k16.row.col.f32.f16.f16.f32 " \
        "{%0,%1,%2,%3},{%4,%5,%6,%7},{%8,%9},{%0,%1,%2,%3};" \
        : "+f"((d)[0]), "+f"((d)[1]), "+f"((d)[2]), "+f"((d)[3]) \
        : "r"((a)[0]), "r"((a)[1]), "r"((a)[2]), "r"((a)[3]), "r"(b0), "r"(b1))
#define CPASYNC16(dst, src, sz) \
    asm volatile("cp.async.cg.shared.global [%0], [%1], 16, %2;" \
        :: "r"(dst), "l"(src), "r"(sz) : "memory")
#define CPCOMMIT() asm volatile("cp.async.commit_group;" ::: "memory")

__global__ __launch_bounds__(256, 2) void mma_gemm(
    const __half* __restrict__ Ah, const __half* __restrict__ Al,
    const __half* __restrict__ Bf,
    __half* __restrict__ Ch, int M, int K)
{
    __shared__ __half sAh[3][TBM][APAD];
    __shared__ __half sAl[3][TBM][APAD];
    __shared__ __half sB [3][TBK][BPAD];

    int tid = threadIdx.x;
    int warp = tid >> 5, lane = tid & 31;
    int wm = warp >> 2, wn = warp & 3;           // 2x4 warp grid, warp tile m64 x n32
    int block_row = blockIdx.x * TBM;
    int block_col = blockIdx.y * TBN;

    float acc[4][4][4];
    #pragma unroll
    for (int i = 0; i < 4; i++)
        #pragma unroll
        for (int j = 0; j < 4; j++)
            #pragma unroll
            for (int k = 0; k < 4; k++) acc[i][j][k] = 0.0f;

    auto issueStage = [&](int st, int k0) {
        #pragma unroll
        for (int q = 0; q < 2; q++) {
            int g = tid * 2 + q;
            int row = g >> 2, c16 = g & 3;
            int grow = block_row + row;
            int sz = (grow < M) ? 16 : 0;
            const __half* ph = Ah + (size_t)grow * K + k0 + c16 * 8;
            const __half* pl = Al + (size_t)grow * K + k0 + c16 * 8;
            uint32_t dh = (uint32_t)__cvta_generic_to_shared(&sAh[st][row][c16 * 8]);
            uint32_t dl = (uint32_t)__cvta_generic_to_shared(&sAl[st][row][c16 * 8]);
            CPASYNC16(dh, ph, sz);
            CPASYNC16(dl, pl, sz);
        }
        #pragma unroll
        for (int q = 0; q < 2; q++) {
            int g = tid * 2 + q;
            int row = g >> 4, c16 = g & 15;
            const __half* pb = Bf + (size_t)(k0 + row) * HID + block_col + c16 * 8;
            uint32_t db = (uint32_t)__cvta_generic_to_shared(&sB[st][row][c16 * 8]);
            CPASYNC16(db, pb, 16);
        }
    };

    auto mmaStage = [&](int st) {
        #pragma unroll
        for (int ks = 0; ks < 2; ks++) {
            uint32_t afh[4][4], afl[4][4], bf[2][4];
            #pragma unroll
            for (int mi = 0; mi < 4; mi++) {
                int r = wm * 64 + mi * 16 + (lane & 15);
                int c = ks * 16 + (lane >> 4) * 8;
                uint32_t ah = (uint32_t)__cvta_generic_to_shared(&sAh[st][r][c]);
                uint32_t al = (uint32_t)__cvta_generic_to_shared(&sAl[st][r][c]);
                LDSM4(afh[mi], ah);
                LDSM4(afl[mi], al);
            }
            #pragma unroll
            for (int ni = 0; ni < 2; ni++) {
                int r = ks * 16 + (lane & 15);
                int c = wn * 32 + ni * 16 + (lane >> 4) * 8;
                uint32_t bb = (uint32_t)__cvta_generic_to_shared(&sB[st][r][c]);
                LDSM4T(bf[ni], bb);
            }
            #pragma unroll
            for (int mi = 0; mi < 4; mi++)
                #pragma unroll
                for (int n8 = 0; n8 < 4; n8++) {
                    uint32_t b0 = bf[n8 >> 1][(n8 & 1) * 2];
                    uint32_t b1 = bf[n8 >> 1][(n8 & 1) * 2 + 1];
                    MMA16816F(acc[mi][n8], afh[mi], b0, b1);
                    MMA16816F(acc[mi][n8], afl[mi], b0, b1);
                }
        }
    };

    int nIters = K / TBK;
    issueStage(0, 0);
    CPCOMMIT();
    issueStage(1, TBK);
    CPCOMMIT();

    for (int it = 0; it < nIters; it++) {
        int cur = it % 3;
        asm volatile("cp.async.wait_group 1;" ::: "memory");
        __syncthreads();
        mmaStage(cur);
        if (it + 2 < nIters) issueStage((it + 2) % 3, (it + 2) * TBK);
        CPCOMMIT();
    }

    // epilogue: write h as fp16
    #pragma unroll
    for (int mi = 0; mi < 4; mi++) {
        #pragma unroll
        for (int n8 = 0; n8 < 4; n8++) {
            int col = block_col + wn * 32 + n8 * 8 + (lane & 3) * 2;
            #pragma unroll
            for (int h = 0; h < 2; h++) {
                int row = block_row + wm * 64 + mi * 16 + (lane >> 2) + h * 8;
                if (row < M) {
                    *(__half2*)(Ch + (size_t)row * HID + col) =
                        __floats2half2_rn(acc[mi][n8][h * 2], acc[mi][n8][h * 2 + 1]);
                }
            }
        }
    }
}

// ---------------- pull aggregation + fused BN stats (fp16 gather, unroll-8) -----------
// lane handles columns [lane*8, lane*8+8): one uint4 (8 halves) per row per lane.
__global__ __launch_bounds__(256) void aggregate(
    const __half* __restrict__ h, const float* __restrict__ bias,
    float* __restrict__ agg, float* __restrict__ sum, float* __restrict__ sq, int N)
{
    int lane = threadIdx.x & 31;
    int w    = threadIdx.x >> 5;
    int wId  = (blockIdx.x << 3) + w;
    int nW   = gridDim.x << 3;

    float4 bv0 = ((const float4*)bias)[lane * 2];
    float4 bv1 = ((const float4*)bias)[lane * 2 + 1];
    float4 cs0 = make_float4(0,0,0,0), cq0 = make_float4(0,0,0,0);
    float4 cs1 = make_float4(0,0,0,0), cq1 = make_float4(0,0,0,0);

    for (int d = wId; d < N; d += nW) {
        int beg = g_rowp[d], end = g_rowp[d + 1];
        float id = g_invdeg[d];
        uint4 sv = ((const uint4*)(h + (size_t)d * HID))[lane];
        float4 a0 = bv0, a1 = bv1;
        fma8(sv, id, a0, a1);

        int j = beg;
        for (; j + 8 <= end; j += 8) {
            int   s0 = g_esrc[j],     s1 = g_esrc[j + 1];
            int   s2 = g_esrc[j + 2], s3 = g_esrc[j + 3];
            int   s4 = g_esrc[j + 4], s5 = g_esrc[j + 5];
            int   s6 = g_esrc[j + 6], s7 = g_esrc[j + 7];
            float c0 = g_ecoef[j],     c1 = g_ecoef[j + 1];
            float c2 = g_ecoef[j + 2], c3 = g_ecoef[j + 3];
            float c4 = g_ecoef[j + 4], c5 = g_ecoef[j + 5];
            float c6 = g_ecoef[j + 6], c7 = g_ecoef[j + 7];
            uint4 v0 = ((const uint4*)(h + (size_t)s0 * HID))[lane];
            uint4 v1 = ((const uint4*)(h + (size_t)s1 * HID))[lane];
            uint4 v2 = ((const uint4*)(h + (size_t)s2 * HID))[lane];
            uint4 v3 = ((const uint4*)(h + (size_t)s3 * HID))[lane];
            uint4 v4 = ((const uint4*)(h + (size_t)s4 * HID))[lane];
            uint4 v5 = ((const uint4*)(h + (size_t)s5 * HID))[lane];
            uint4 v6 = ((const uint4*)(h + (size_t)s6 * HID))[lane];
            uint4 v7 = ((const uint4*)(h + (size_t)s7 * HID))[lane];
            fma8(v0, c0, a0, a1); fma8(v1, c1, a0, a1);
            fma8(v2, c2, a0, a1); fma8(v3, c3, a0, a1);
            fma8(v4, c4, a0, a1); fma8(v5, c5, a0, a1);
            fma8(v6, c6, a0, a1); fma8(v7, c7, a0, a1);
        }
        for (; j + 4 <= end; j += 4) {
            int   s0 = g_esrc[j],     s1 = g_esrc[j + 1];
            int   s2 = g_esrc[j + 2], s3 = g_esrc[j + 3];
            float c0 = g_ecoef[j],     c1 = g_ecoef[j + 1];
            float c2 = g_ecoef[j + 2], c3 = g_ecoef[j + 3];
            uint4 v0 = ((const uint4*)(h + (size_t)s0 * HID))[lane];
            uint4 v1 = ((const uint4*)(h + (size_t)s1 * HID))[lane];
            uint4 v2 = ((const uint4*)(h + (size_t)s2 * HID))[lane];
            uint4 v3 = ((const uint4*)(h + (size_t)s3 * HID))[lane];
            fma8(v0, c0, a0, a1); fma8(v1, c1, a0, a1);
            fma8(v2, c2, a0, a1); fma8(v3, c3, a0, a1);
        }
        for (; j < end; j++) {
            int s  = g_esrc[j];
            float c = g_ecoef[j];
            uint4 v = ((const uint4*)(h + (size_t)s * HID))[lane];
            fma8(v, c, a0, a1);
        }

        float4* ad = (float4*)(agg + (size_t)d * HID);
        ad[lane * 2]     = a0;
        ad[lane * 2 + 1] = a1;
        f4acc(cs0, a0); f4accsq(cq0, a0);
        f4acc(cs1, a1); f4accsq(cq1, a1);
    }

    // block-level stat reduction; lane covers cols [lane*8, lane*8+8) in every warp
    __shared__ float4 rs0[8][32], rq0[8][32], rs1[8][32], rq1[8][32];
    rs0[w][lane] = cs0; rq0[w][lane] = cq0;
    rs1[w][lane] = cs1; rq1[w][lane] = cq1;
    __syncthreads();
    if (w == 0) {
        float4 ts0 = rs0[0][lane], tq0 = rq0[0][lane];
        float4 ts1 = rs1[0][lane], tq1 = rq1[0][lane];
        #pragma unroll
        for (int i = 1; i < 8; i++) {
            f4acc(ts0, rs0[i][lane]); f4acc(tq0, rq0[i][lane]);
            f4acc(ts1, rs1[i][lane]); f4acc(tq1, rq1[i][lane]);
        }
        int c0 = lane * 8;
        atomicAdd(&sum[c0+0], ts0.x); atomicAdd(&sum[c0+1], ts0.y);
        atomicAdd(&sum[c0+2], ts0.z); atomicAdd(&sum[c0+3], ts0.w);
        atomicAdd(&sum[c0+4], ts1.x); atomicAdd(&sum[c0+5], ts1.y);
        atomicAdd(&sum[c0+6], ts1.z); atomicAdd(&sum[c0+7], ts1.w);
        atomicAdd(&sq[c0+0],  tq0.x); atomicAdd(&sq[c0+1],  tq0.y);
        atomicAdd(&sq[c0+2],  tq0.z); atomicAdd(&sq[c0+3],  tq0.w);
        atomicAdd(&sq[c0+4],  tq1.x); atomicAdd(&sq[c0+5],  tq1.y);
        atomicAdd(&sq[c0+6],  tq1.z); atomicAdd(&sq[c0+7],  tq1.w);
    }
}

// ---------------- BN coef (1 block) ----------------
__global__ void bn_coef(const float* __restrict__ sum, const float* __restrict__ sq,
                        const float* __restrict__ gamma, const float* __restrict__ beta,
                        float* __restrict__ ga, float* __restrict__ bb, int N) {
    int c = threadIdx.x;
    float invN = 1.0f / (float)N;
    float mu  = sum[c] * invN;
    float var = sq[c] * invN - mu * mu;
    float rs  = rsqrtf(var + BN_EPS);
    float g   = gamma[c] * rs;
    ga[c] = g;
    bb[c] = beta[c] - mu * g;
}

// ---------------- BN apply + ReLU (final output) ----------------
__global__ __launch_bounds__(256) void bn_apply2(float* __restrict__ a,
                                                 const float* __restrict__ ga,
                                                 const float* __restrict__ bb, int N) {
    int i = blockIdx.x * blockDim.x + threadIdx.x;
    int total = N * (HID / 4);
    if (i >= total) return;
    int c4 = i & 63;
    float4 v = ((float4*)a)[i];
    float4 g = ((const float4*)ga)[c4];
    float4 b = ((const float4*)bb)[c4];
    v.x = fmaxf(0.f, fmaf(v.x, g.x, b.x));
    v.y = fmaxf(0.f, fmaf(v.y, g.y, b.y));
    v.z = fmaxf(0.f, fmaf(v.z, g.z, b.z));
    v.w = fmaxf(0.f, fmaf(v.w, g.w, b.w));
    ((float4*)a)[i] = v;
}

// ---------------- launch ----------------
extern "C" void kernel_launch(void* const* d_in, const int* in_sizes, int n_in,
                              void* d_out, int out_size) {
    const float* x   = (const float*)d_in[0];
    const int*   ei  = (const int*)d_in[1];
    const float* W1  = (const float*)d_in[2];
    const float* b1  = (const float*)d_in[3];
    const float* g1  = (const float*)d_in[4];
    const float* be1 = (const float*)d_in[5];
    const float* W2  = (const float*)d_in[6];
    const float* b2  = (const float*)d_in[7];
    const float* g2  = (const float*)d_in[8];
    const float* be2 = (const float*)d_in[9];
    float* out = (float*)d_out;

    const int IN_DIM = IN_DIM_C;
    int N = in_sizes[0] / IN_DIM;
    int E = in_sizes[1] / 2;
    const int* src = ei;
    const int* dst = ei + E;

    float *aP, *statsP, *coefP;
    cudaGetSymbolAddress((void**)&aP, g_a);
    cudaGetSymbolAddress((void**)&statsP, g_stats);
    cudaGetSymbolAddress((void**)&coefP, g_coef);
    __half *w1f, *w2f, *ahP, *alP, *hH;
    cudaGetSymbolAddress((void**)&w1f, g_W1f);
    cudaGetSymbolAddress((void**)&w2f, g_W2f);
    cudaGetSymbolAddress((void**)&ahP, g_Ah);
    cudaGetSymbolAddress((void**)&alP, g_Al);
    cudaGetSymbolAddress((void**)&hH, g_hH);

    int nb256 = (N + 255) / 256;
    int aggBlocks  = 592;
    int outBlocks  = (N * (HID / 4) + 255) / 256;
    dim3 gemmGrid((N + TBM - 1) / TBM, HID / TBN);
    int cv1 = N * (IN_DIM / 4);
    int cv2 = N * (HID / 4);

    // graph structure + CSR + weight rounding
    zero_kernel<<<nb256, 256>>>(N);
    deg_count<<<(E + 255) / 256, 256>>>(dst, E);
    wsplit<<<(IN_DIM * HID + 255) / 256, 256>>>(W1, W2);
    scan1<<<nb256, 256>>>(N);
    scan2<<<1, 512>>>(nb256);
    scan3<<<(N + 256) / 256, 256>>>(N, E);
    csr_fill<<<(E + 255) / 256, 256>>>(src, dst, E);

    // ---- layer 1 ----
    convertA<false><<<(cv1 + 255) / 256, 256>>>(x, nullptr, nullptr, cv1, IN_DIM / 4);
    mma_gemm<<<gemmGrid, 256>>>(ahP, alP, w1f, hH, N, IN_DIM);
    aggregate<<<aggBlocks, 256>>>(hH, b1, aP, statsP + 0, statsP + HID, N);
    bn_coef<<<1, 256>>>(statsP + 0, statsP + HID, g1, be1, coefP + 0, coefP + HID, N);

    // ---- layer 2 (BN1+ReLU fused into convert) ----
    convertA<true><<<(cv2 + 255) / 256, 256>>>(aP, coefP + 0, coefP + HID, cv2, HID / 4);
    mma_gemm<<<gemmGrid, 256>>>(ahP, alP, w2f, hH, N, HID);
    aggregate<<<aggBlocks, 256>>>(hH, b2, out, statsP + 2 * HID, statsP + 3 * HID, N);
    bn_coef<<<1, 256>>>(statsP + 2 * HID, statsP + 3 * HID, g2, be2,
                        coefP + 2 * HID, coefP + 3 * HID, N);
    bn_apply2<<<outBlocks, 256>>>(out, coefP + 2 * HID, coefP + 3 * HID, N);
}

// round 15
// speedup vs baseline: 1.2141x; 1.0181x over previous
#include <cuda_runtime.h>
#include <cuda_bf16.h>
#include <cuda_fp16.h>
#include <math.h>
#include <stdint.h>

// GNNEncoder: N=100000 nodes, E=800000 edges, 384 -> 256 -> 256
#define MAXN 100000
#define MAXE 800000
#define HID  256
#define IN_DIM_C 384
#define BN_EPS 1e-5f

// ---------------- device scratch ----------------
__device__ __half g_hH[(size_t)MAXN * HID];    // GEMM output, fp16 (gather-optimized)
__device__ float g_a[(size_t)MAXN * HID];
__device__ int   g_deg[MAXN];
__device__ int   g_fill[MAXN];
__device__ int   g_rowp[MAXN + 1];
__device__ int   g_blksum[512];
__device__ int   g_blkoff[512];
__device__ int   g_esrc[MAXE];
__device__ float g_ecoef[MAXE];
__device__ float g_dinv[MAXN];
__device__ float g_invdeg[MAXN];
__device__ float g_stats[4 * HID];   // sum1, sq1, sum2, sq2
__device__ float g_coef[4 * HID];    // ga1, bb1, ga2, bb2
// fp16 weights (round-to-nearest), layout [K][N]
__device__ __half g_W1f[IN_DIM_C * HID];
__device__ __half g_W2f[HID * HID];
// fp16 split activations (hi/lo), layout [M][K]
__device__ __half g_Ah[(size_t)MAXN * IN_DIM_C];
__device__ __half g_Al[(size_t)MAXN * IN_DIM_C];

// ---------------- helpers ----------------
__device__ __forceinline__ void f4acc(float4& d, float4 v) {
    d.x += v.x; d.y += v.y; d.z += v.z; d.w += v.w;
}
__device__ __forceinline__ void f4accsq(float4& d, float4 v) {
    d.x = fmaf(v.x, v.x, d.x); d.y = fmaf(v.y, v.y, d.y);
    d.z = fmaf(v.z, v.z, d.z); d.w = fmaf(v.w, v.w, d.w);
}
// 8 halves (uint4) -> two float4
__device__ __forceinline__ void h8tof8(uint4 v, float4& f0, float4& f1) {
    __half2* p = (__half2*)&v;
    float2 x0 = __half22float2(p[0]);
    float2 x1 = __half22float2(p[1]);
    float2 x2 = __half22float2(p[2]);
    float2 x3 = __half22float2(p[3]);
    f0 = make_float4(x0.x, x0.y, x1.x, x1.y);
    f1 = make_float4(x2.x, x2.y, x3.x, x3.y);
}
__device__ __forceinline__ void fma8(uint4 v, float c, float4& a0, float4& a1) {
    float4 f0, f1;
    h8tof8(v, f0, f1);
    a0.x = fmaf(f0.x, c, a0.x); a0.y = fmaf(f0.y, c, a0.y);
    a0.z = fmaf(f0.z, c, a0.z); a0.w = fmaf(f0.w, c, a0.w);
    a1.x = fmaf(f1.x, c, a1.x); a1.y = fmaf(f1.y, c, a1.y);
    a1.z = fmaf(f1.z, c, a1.z); a1.w = fmaf(f1.w, c, a1.w);
}

// ---------------- init / degree ----------------
__global__ void zero_kernel(int N) {
    int i = blockIdx.x * blockDim.x + threadIdx.x;
    if (i < N) { g_deg[i] = 0; g_fill[i] = 0; }
    if (i < 4 * HID) g_stats[i] = 0.0f;
}

__global__ void deg_count(const int* __restrict__ dst, int E) {
    int i = blockIdx.x * blockDim.x + threadIdx.x;
    if (i < E) atomicAdd(&g_deg[dst[i]], 1);
}

// ---------------- weight fp16 round ----------------
__global__ void wsplit(const float* __restrict__ W1, const float* __restrict__ W2) {
    int i = blockIdx.x * blockDim.x + threadIdx.x;
    if (i < IN_DIM_C * HID) g_W1f[i] = __float2half_rn(W1[i]);
    if (i < HID * HID)      g_W2f[i] = __float2half_rn(W2[i]);
}

// ---------------- activation fp16 split (optionally fused BN+ReLU) ----------------
template<bool BNA>
__global__ __launch_bounds__(256) void convertA(const float* __restrict__ src,
                                                const float* __restrict__ ga,
                                                const float* __restrict__ bb,
                                                int total4, int kq) {   // kq = K/4
    int i = blockIdx.x * blockDim.x + threadIdx.x;
    if (i >= total4) return;
    float4 v = ((const float4*)src)[i];
    if (BNA) {
        int c4 = i % kq;
        float4 g = ((const float4*)ga)[c4];
        float4 b = ((const float4*)bb)[c4];
        v.x = fmaxf(0.f, fmaf(v.x, g.x, b.x));
        v.y = fmaxf(0.f, fmaf(v.y, g.y, b.y));
        v.z = fmaxf(0.f, fmaf(v.z, g.z, b.z));
        v.w = fmaxf(0.f, fmaf(v.w, g.w, b.w));
    }
    __half hx = __float2half_rn(v.x);
    __half hy = __float2half_rn(v.y);
    __half hz = __float2half_rn(v.z);
    __half hw = __float2half_rn(v.w);
    __half2 h01 = __halves2half2(hx, hy);
    __half2 h23 = __halves2half2(hz, hw);
    __half2 l01 = __halves2half2(__float2half_rn(v.x - __half2float(hx)),
                                 __float2half_rn(v.y - __half2float(hy)));
    __half2 l23 = __halves2half2(__float2half_rn(v.z - __half2float(hz)),
                                 __float2half_rn(v.w - __half2float(hw)));
    uint2 hp, lp;
    hp.x = *(uint32_t*)&h01; hp.y = *(uint32_t*)&h23;
    lp.x = *(uint32_t*)&l01; lp.y = *(uint32_t*)&l23;
    ((uint2*)g_Ah)[i] = hp;
    ((uint2*)g_Al)[i] = lp;
}

// ---------------- scan of g_deg -> g_rowp + dinv/invdeg (fused) ----------------
__global__ void scan1(int N) {
    __shared__ int s[256];
    int t = threadIdx.x;
    int i = blockIdx.x * 256 + t;
    int v = (i < N) ? g_deg[i] : 0;
    if (i < N) {
        float dg = (float)v + 1.0f;
        g_dinv[i]   = rsqrtf(dg);
        g_invdeg[i] = 1.0f / dg;
    }
    s[t] = v; __syncthreads();
    #pragma unroll
    for (int off = 1; off < 256; off <<= 1) {
        int x = (t >= off) ? s[t - off] : 0;
        __syncthreads();
        s[t] += x;
        __syncthreads();
    }
    if (i < N) g_rowp[i] = s[t] - v;             // exclusive
    if (t == 255) g_blksum[blockIdx.x] = s[t];
}
__global__ void scan2(int nb) {
    __shared__ int s[512];
    int t = threadIdx.x;
    int v = (t < nb) ? g_blksum[t] : 0;
    s[t] = v; __syncthreads();
    #pragma unroll
    for (int off = 1; off < 512; off <<= 1) {
        int x = (t >= off) ? s[t - off] : 0;
        __syncthreads();
        s[t] += x;
        __syncthreads();
    }
    g_blkoff[t] = s[t] - v;
}
__global__ void scan3(int N, int E) {
    int i = blockIdx.x * 256 + threadIdx.x;
    if (i < N) g_rowp[i] += g_blkoff[i >> 8];
    if (i == 0) g_rowp[N] = E;
}

// ---------------- CSR fill ----------------
__global__ void csr_fill(const int* __restrict__ src, const int* __restrict__ dst, int E) {
    int e = blockIdx.x * blockDim.x + threadIdx.x;
    if (e >= E) return;
    int s = src[e], d = dst[e];
    int pos = g_rowp[d] + atomicAdd(&g_fill[d], 1);
    g_esrc[pos]  = s;
    g_ecoef[pos] = g_dinv[s] * g_dinv[d];
}

// ---------------- tensor-core GEMM (fp16 hi/lo A x fp16 B, 3-stage cp.async) ---------
#define TBM 128
#define TBN 128
#define TBK 32
#define APAD 40      // row = 80B
#define BPAD 136     // row = 272B

#define LDSM4(R, addr) \
    asm volatile("ldmatrix.sync.aligned.m8n8.x4.shared.b16 {%0,%1,%2,%3}, [%4];" \
        : "=r"((R)[0]), "=r"((R)[1]), "=r"((R)[2]), "=r"((R)[3]) : "r"(addr))
#define LDSM4T(R, addr) \
    asm volatile("ldmatrix.sync.aligned.m8n8.x4.trans.shared.b16 {%0,%1,%2,%3}, [%4];" \
        : "=r"((R)[0]), "=r"((R)[1]), "=r"((R)[2]), "=r"((R)[3]) : "r"(addr))
#define MMA16816F(d, a, b0, b1) \
    asm volatile("mma.sync.aligned.m16n8k16.row.col.f32.f16.f16.f32 " \
        "{%0,%1,%2,%3},{%4,%5,%6,%7},{%8,%9},{%0,%1,%2,%3};" \
        : "+f"((d)[0]), "+f"((d)[1]), "+f"((d)[2]), "+f"((d)[3]) \
        : "r"((a)[0]), "r"((a)[1]), "r"((a)[2]), "r"((a)[3]), "r"(b0), "r"(b1))
#define CPASYNC16(dst, src, sz) \
    asm volatile("cp.async.cg.shared.global [%0], [%1], 16, %2;" \
        :: "r"(dst), "l"(src), "r"(sz) : "memory")
#define CPCOMMIT() asm volatile("cp.async.commit_group;" ::: "memory")

__global__ __launch_bounds__(256, 2) void mma_gemm(
    const __half* __restrict__ Ah, const __half* __restrict__ Al,
    const __half* __restrict__ Bf,
    __half* __restrict__ Ch, int M, int K)
{
    __shared__ __half sAh[3][TBM][APAD];
    __shared__ __half sAl[3][TBM][APAD];
    __shared__ __half sB [3][TBK][BPAD];

    int tid = threadIdx.x;
    int warp = tid >> 5, lane = tid & 31;
    int wm = warp >> 2, wn = warp & 3;           // 2x4 warp grid, warp tile m64 x n32
    int block_row = blockIdx.x * TBM;
    int block_col = blockIdx.y * TBN;

    float acc[4][4][4];
    #pragma unroll
    for (int i = 0; i < 4; i++)
        #pragma unroll
        for (int j = 0; j < 4; j++)
            #pragma unroll
            for (int k = 0; k < 4; k++) acc[i][j][k] = 0.0f;

    auto issueStage = [&](int st, int k0) {
        #pragma unroll
        for (int q = 0; q < 2; q++) {
            int g = tid * 2 + q;
            int row = g >> 2, c16 = g & 3;
            int grow = block_row + row;
            int sz = (grow < M) ? 16 : 0;
            const __half* ph = Ah + (size_t)grow * K + k0 + c16 * 8;
            const __half* pl = Al + (size_t)grow * K + k0 + c16 * 8;
            uint32_t dh = (uint32_t)__cvta_generic_to_shared(&sAh[st][row][c16 * 8]);
            uint32_t dl = (uint32_t)__cvta_generic_to_shared(&sAl[st][row][c16 * 8]);
            CPASYNC16(dh, ph, sz);
            CPASYNC16(dl, pl, sz);
        }
        #pragma unroll
        for (int q = 0; q < 2; q++) {
            int g = tid * 2 + q;
            int row = g >> 4, c16 = g & 15;
            const __half* pb = Bf + (size_t)(k0 + row) * HID + block_col + c16 * 8;
            uint32_t db = (uint32_t)__cvta_generic_to_shared(&sB[st][row][c16 * 8]);
            CPASYNC16(db, pb, 16);
        }
    };

    auto mmaStage = [&](int st) {
        #pragma unroll
        for (int ks = 0; ks < 2; ks++) {
            uint32_t afh[4][4], afl[4][4], bf[2][4];
            #pragma unroll
            for (int mi = 0; mi < 4; mi++) {
                int r = wm * 64 + mi * 16 + (lane & 15);
                int c = ks * 16 + (lane >> 4) * 8;
                uint32_t ah = (uint32_t)__cvta_generic_to_shared(&sAh[st][r][c]);
                uint32_t al = (uint32_t)__cvta_generic_to_shared(&sAl[st][r][c]);
                LDSM4(afh[mi], ah);
                LDSM4(afl[mi], al);
            }
            #pragma unroll
            for (int ni = 0; ni < 2; ni++) {
                int r = ks * 16 + (lane & 15);
                int c = wn * 32 + ni * 16 + (lane >> 4) * 8;
                uint32_t bb = (uint32_t)__cvta_generic_to_shared(&sB[st][r][c]);
                LDSM4T(bf[ni], bb);
            }
            #pragma unroll
            for (int mi = 0; mi < 4; mi++)
                #pragma unroll
                for (int n8 = 0; n8 < 4; n8++) {
                    uint32_t b0 = bf[n8 >> 1][(n8 & 1) * 2];
                    uint32_t b1 = bf[n8 >> 1][(n8 & 1) * 2 + 1];
                    MMA16816F(acc[mi][n8], afh[mi], b0, b1);
                    MMA16816F(acc[mi][n8], afl[mi], b0, b1);
                }
        }
    };

    int nIters = K / TBK;
    issueStage(0, 0);
    CPCOMMIT();
    issueStage(1, TBK);
    CPCOMMIT();

    for (int it = 0; it < nIters; it++) {
        int cur = it % 3;
        asm volatile("cp.async.wait_group 1;" ::: "memory");
        __syncthreads();
        mmaStage(cur);
        if (it + 2 < nIters) issueStage((it + 2) % 3, (it + 2) * TBK);
        CPCOMMIT();
    }

    // epilogue: write h as fp16
    #pragma unroll
    for (int mi = 0; mi < 4; mi++) {
        #pragma unroll
        for (int n8 = 0; n8 < 4; n8++) {
            int col = block_col + wn * 32 + n8 * 8 + (lane & 3) * 2;
            #pragma unroll
            for (int h = 0; h < 2; h++) {
                int row = block_row + wm * 64 + mi * 16 + (lane >> 2) + h * 8;
                if (row < M) {
                    *(__half2*)(Ch + (size_t)row * HID + col) =
                        __floats2half2_rn(acc[mi][n8][h * 2], acc[mi][n8][h * 2 + 1]);
                }
            }
        }
    }
}

// ---------------- pull aggregation + fused BN stats (fp16 gather, unroll-8) -----------
__global__ __launch_bounds__(256) void aggregate(
    const __half* __restrict__ h, const float* __restrict__ bias,
    float* __restrict__ agg, float* __restrict__ sum, float* __restrict__ sq, int N)
{
    int lane = threadIdx.x & 31;
    int w    = threadIdx.x >> 5;
    int wId  = (blockIdx.x << 3) + w;
    int nW   = gridDim.x << 3;

    float4 bv0 = ((const float4*)bias)[lane * 2];
    float4 bv1 = ((const float4*)bias)[lane * 2 + 1];
    float4 cs0 = make_float4(0,0,0,0), cq0 = make_float4(0,0,0,0);
    float4 cs1 = make_float4(0,0,0,0), cq1 = make_float4(0,0,0,0);

    for (int d = wId; d < N; d += nW) {
        int beg = g_rowp[d], end = g_rowp[d + 1];
        float id = g_invdeg[d];
        uint4 sv = ((const uint4*)(h + (size_t)d * HID))[lane];
        float4 a0 = bv0, a1 = bv1;
        fma8(sv, id, a0, a1);

        int j = beg;
        for (; j + 8 <= end; j += 8) {
            int   s0 = g_esrc[j],     s1 = g_esrc[j + 1];
            int   s2 = g_esrc[j + 2], s3 = g_esrc[j + 3];
            int   s4 = g_esrc[j + 4], s5 = g_esrc[j + 5];
            int   s6 = g_esrc[j + 6], s7 = g_esrc[j + 7];
            float c0 = g_ecoef[j],     c1 = g_ecoef[j + 1];
            float c2 = g_ecoef[j + 2], c3 = g_ecoef[j + 3];
            float c4 = g_ecoef[j + 4], c5 = g_ecoef[j + 5];
            float c6 = g_ecoef[j + 6], c7 = g_ecoef[j + 7];
            uint4 v0 = ((const uint4*)(h + (size_t)s0 * HID))[lane];
            uint4 v1 = ((const uint4*)(h + (size_t)s1 * HID))[lane];
            uint4 v2 = ((const uint4*)(h + (size_t)s2 * HID))[lane];
            uint4 v3 = ((const uint4*)(h + (size_t)s3 * HID))[lane];
            uint4 v4 = ((const uint4*)(h + (size_t)s4 * HID))[lane];
            uint4 v5 = ((const uint4*)(h + (size_t)s5 * HID))[lane];
            uint4 v6 = ((const uint4*)(h + (size_t)s6 * HID))[lane];
            uint4 v7 = ((const uint4*)(h + (size_t)s7 * HID))[lane];
            fma8(v0, c0, a0, a1); fma8(v1, c1, a0, a1);
            fma8(v2, c2, a0, a1); fma8(v3, c3, a0, a1);
            fma8(v4, c4, a0, a1); fma8(v5, c5, a0, a1);
            fma8(v6, c6, a0, a1); fma8(v7, c7, a0, a1);
        }
        for (; j + 4 <= end; j += 4) {
            int   s0 = g_esrc[j],     s1 = g_esrc[j + 1];
            int   s2 = g_esrc[j + 2], s3 = g_esrc[j + 3];
            float c0 = g_ecoef[j],     c1 = g_ecoef[j + 1];
            float c2 = g_ecoef[j + 2], c3 = g_ecoef[j + 3];
            uint4 v0 = ((const uint4*)(h + (size_t)s0 * HID))[lane];
            uint4 v1 = ((const uint4*)(h + (size_t)s1 * HID))[lane];
            uint4 v2 = ((const uint4*)(h + (size_t)s2 * HID))[lane];
            uint4 v3 = ((const uint4*)(h + (size_t)s3 * HID))[lane];
            fma8(v0, c0, a0, a1); fma8(v1, c1, a0, a1);
            fma8(v2, c2, a0, a1); fma8(v3, c3, a0, a1);
        }
        for (; j < end; j++) {
            int s  = g_esrc[j];
            float c = g_ecoef[j];
            uint4 v = ((const uint4*)(h + (size_t)s * HID))[lane];
            fma8(v, c, a0, a1);
        }

        float4* ad = (float4*)(agg + (size_t)d * HID);
        ad[lane * 2]     = a0;
        ad[lane * 2 + 1] = a1;
        f4acc(cs0, a0); f4accsq(cq0, a0);
        f4acc(cs1, a1); f4accsq(cq1, a1);
    }

    __shared__ float4 rs0[8][32], rq0[8][32], rs1[8][32], rq1[8][32];
    rs0[w][lane] = cs0; rq0[w][lane] = cq0;
    rs1[w][lane] = cs1; rq1[w][lane] = cq1;
    __syncthreads();
    if (w == 0) {
        float4 ts0 = rs0[0][lane], tq0 = rq0[0][lane];
        float4 ts1 = rs1[0][lane], tq1 = rq1[0][lane];
        #pragma unroll
        for (int i = 1; i < 8; i++) {
            f4acc(ts0, rs0[i][lane]); f4acc(tq0, rq0[i][lane]);
            f4acc(ts1, rs1[i][lane]); f4acc(tq1, rq1[i][lane]);
        }
        int c0 = lane * 8;
        atomicAdd(&sum[c0+0], ts0.x); atomicAdd(&sum[c0+1], ts0.y);
        atomicAdd(&sum[c0+2], ts0.z); atomicAdd(&sum[c0+3], ts0.w);
        atomicAdd(&sum[c0+4], ts1.x); atomicAdd(&sum[c0+5], ts1.y);
        atomicAdd(&sum[c0+6], ts1.z); atomicAdd(&sum[c0+7], ts1.w);
        atomicAdd(&sq[c0+0],  tq0.x); atomicAdd(&sq[c0+1],  tq0.y);
        atomicAdd(&sq[c0+2],  tq0.z); atomicAdd(&sq[c0+3],  tq0.w);
        atomicAdd(&sq[c0+4],  tq1.x); atomicAdd(&sq[c0+5],  tq1.y);
        atomicAdd(&sq[c0+6],  tq1.z); atomicAdd(&sq[c0+7],  tq1.w);
    }
}

// ---------------- BN coef (1 block) ----------------
__global__ void bn_coef(const float* __restrict__ sum, const float* __restrict__ sq,
                        const float* __restrict__ gamma, const float* __restrict__ beta,
                        float* __restrict__ ga, float* __restrict__ bb, int N) {
    int c = threadIdx.x;
    float invN = 1.0f / (float)N;
    float mu  = sum[c] * invN;
    float var = sq[c] * invN - mu * mu;
    float rs  = rsqrtf(var + BN_EPS);
    float g   = gamma[c] * rs;
    ga[c] = g;
    bb[c] = beta[c] - mu * g;
}

// ---------------- BN apply + ReLU (final output) ----------------
__global__ __launch_bounds__(256) void bn_apply2(float* __restrict__ a,
                                                 const float* __restrict__ ga,
                                                 const float* __restrict__ bb, int N) {
    int i = blockIdx.x * blockDim.x + threadIdx.x;
    int total = N * (HID / 4);
    if (i >= total) return;
    int c4 = i & 63;
    float4 v = ((float4*)a)[i];
    float4 g = ((const float4*)ga)[c4];
    float4 b = ((const float4*)bb)[c4];
    v.x = fmaxf(0.f, fmaf(v.x, g.x, b.x));
    v.y = fmaxf(0.f, fmaf(v.y, g.y, b.y));
    v.z = fmaxf(0.f, fmaf(v.z, g.z, b.z));
    v.w = fmaxf(0.f, fmaf(v.w, g.w, b.w));
    ((float4*)a)[i] = v;
}

// ---------------- launch (fork/join: CSR build ∥ convert+GEMM1) ----------------
extern "C" void kernel_launch(void* const* d_in, const int* in_sizes, int n_in,
                              void* d_out, int out_size) {
    const float* x   = (const float*)d_in[0];
    const int*   ei  = (const int*)d_in[1];
    const float* W1  = (const float*)d_in[2];
    const float* b1  = (const float*)d_in[3];
    const float* g1  = (const float*)d_in[4];
    const float* be1 = (const float*)d_in[5];
    const float* W2  = (const float*)d_in[6];
    const float* b2  = (const float*)d_in[7];
    const float* g2  = (const float*)d_in[8];
    const float* be2 = (const float*)d_in[9];
    float* out = (float*)d_out;

    const int IN_DIM = IN_DIM_C;
    int N = in_sizes[0] / IN_DIM;
    int E = in_sizes[1] / 2;
    const int* src = ei;
    const int* dst = ei + E;

    float *aP, *statsP, *coefP;
    cudaGetSymbolAddress((void**)&aP, g_a);
    cudaGetSymbolAddress((void**)&statsP, g_stats);
    cudaGetSymbolAddress((void**)&coefP, g_coef);
    __half *w1f, *w2f, *ahP, *alP, *hH;
    cudaGetSymbolAddress((void**)&w1f, g_W1f);
    cudaGetSymbolAddress((void**)&w2f, g_W2f);
    cudaGetSymbolAddress((void**)&ahP, g_Ah);
    cudaGetSymbolAddress((void**)&alP, g_Al);
    cudaGetSymbolAddress((void**)&hH, g_hH);

    int nb256 = (N + 255) / 256;
    int aggBlocks  = 592;
    int outBlocks  = (N * (HID / 4) + 255) / 256;
    dim3 gemmGrid((N + TBM - 1) / TBM, HID / TBN);
    int cv1 = N * (IN_DIM / 4);
    int cv2 = N * (HID / 4);

    // side stream for the CSR build (host objects only; created/destroyed per call)
    cudaStream_t s2;
    cudaStreamCreateWithFlags(&s2, cudaStreamNonBlocking);
    cudaEvent_t eFork, eJoin;
    cudaEventCreateWithFlags(&eFork, cudaEventDisableTiming);
    cudaEventCreateWithFlags(&eJoin, cudaEventDisableTiming);

    // fork
    cudaEventRecord(eFork, 0);
    cudaStreamWaitEvent(s2, eFork, 0);

    // ---- branch B (s2): graph structure + CSR ----
    zero_kernel<<<nb256, 256, 0, s2>>>(N);
    deg_count<<<(E + 255) / 256, 256, 0, s2>>>(dst, E);
    scan1<<<nb256, 256, 0, s2>>>(N);
    scan2<<<1, 512, 0, s2>>>(nb256);
    scan3<<<(N + 256) / 256, 256, 0, s2>>>(N, E);
    csr_fill<<<(E + 255) / 256, 256, 0, s2>>>(src, dst, E);
    cudaEventRecord(eJoin, s2);

    // ---- branch A (default stream): weights + convert + GEMM1 ----
    wsplit<<<(IN_DIM * HID + 255) / 256, 256>>>(W1, W2);
    convertA<false><<<(cv1 + 255) / 256, 256>>>(x, nullptr, nullptr, cv1, IN_DIM / 4);
    mma_gemm<<<gemmGrid, 256>>>(ahP, alP, w1f, hH, N, IN_DIM);

    // join before aggregation (needs CSR + stats zero + invdeg)
    cudaStreamWaitEvent(0, eJoin, 0);

    // ---- layer 1 ----
    aggregate<<<aggBlocks, 256>>>(hH, b1, aP, statsP + 0, statsP + HID, N);
    bn_coef<<<1, 256>>>(statsP + 0, statsP + HID, g1, be1, coefP + 0, coefP + HID, N);

    // ---- layer 2 (BN1+ReLU fused into convert) ----
    convertA<true><<<(cv2 + 255) / 256, 256>>>(aP, coefP + 0, coefP + HID, cv2, HID / 4);
    mma_gemm<<<gemmGrid, 256>>>(ahP, alP, w2f, hH, N, HID);
    aggregate<<<aggBlocks, 256>>>(hH, b2, out, statsP + 2 * HID, statsP + 3 * HID, N);
    bn_coef<<<1, 256>>>(statsP + 2 * HID, statsP + 3 * HID, g2, be2,
                        coefP + 2 * HID, coefP + 3 * HID, N);
    bn_apply2<<<outBlocks, 256>>>(out, coefP + 2 * HID, coefP + 3 * HID, N);

    cudaEventDestroy(eFork);
    cudaEventDestroy(eJoin);
    cudaStreamDestroy(s2);
}

// round 16
// speedup vs baseline: 1.4056x; 1.1576x over previous
#include <cuda_runtime.h>
#include <cuda_bf16.h>
#include <cuda_fp16.h>
#include <math.h>
#include <stdint.h>

// GNNEncoder: N=100000 nodes, E=800000 edges, 384 -> 256 -> 256
#define MAXN 100000
#define MAXE 800000
#define HID  256
#define IN_DIM_C 384
#define BN_EPS 1e-5f

// ---------------- device scratch ----------------
__device__ __half g_hH[(size_t)MAXN * HID];    // GEMM output, fp16 (gather-optimized)
__device__ float g_a[(size_t)MAXN * HID];
__device__ int   g_deg[MAXN];
__device__ int   g_fill[MAXN];
__device__ int   g_rowp[MAXN + 1];
__device__ int   g_blksum[512];
__device__ int   g_blkoff[512];
__device__ int   g_esrc[MAXE];
__device__ float g_ecoef[MAXE];
__device__ float g_dinv[MAXN];
__device__ float g_invdeg[MAXN];
__device__ float g_stats[4 * HID];   // sum1, sq1, sum2, sq2
__device__ float g_coef[4 * HID];    // ga1, bb1, ga2, bb2
// fp16 weights (round-to-nearest), layout [K][N]
__device__ __half g_W1f[IN_DIM_C * HID];
__device__ __half g_W2f[HID * HID];
// fp16 activations (round-to-nearest), layout [M][K]
__device__ __half g_Ah[(size_t)MAXN * IN_DIM_C];

// ---------------- helpers ----------------
__device__ __forceinline__ void f4acc(float4& d, float4 v) {
    d.x += v.x; d.y += v.y; d.z += v.z; d.w += v.w;
}
__device__ __forceinline__ void f4accsq(float4& d, float4 v) {
    d.x = fmaf(v.x, v.x, d.x); d.y = fmaf(v.y, v.y, d.y);
    d.z = fmaf(v.z, v.z, d.z); d.w = fmaf(v.w, v.w, d.w);
}
// 8 halves (uint4) -> two float4
__device__ __forceinline__ void h8tof8(uint4 v, float4& f0, float4& f1) {
    __half2* p = (__half2*)&v;
    float2 x0 = __half22float2(p[0]);
    float2 x1 = __half22float2(p[1]);
    float2 x2 = __half22float2(p[2]);
    float2 x3 = __half22float2(p[3]);
    f0 = make_float4(x0.x, x0.y, x1.x, x1.y);
    f1 = make_float4(x2.x, x2.y, x3.x, x3.y);
}
__device__ __forceinline__ void fma8(uint4 v, float c, float4& a0, float4& a1) {
    float4 f0, f1;
    h8tof8(v, f0, f1);
    a0.x = fmaf(f0.x, c, a0.x); a0.y = fmaf(f0.y, c, a0.y);
    a0.z = fmaf(f0.z, c, a0.z); a0.w = fmaf(f0.w, c, a0.w);
    a1.x = fmaf(f1.x, c, a1.x); a1.y = fmaf(f1.y, c, a1.y);
    a1.z = fmaf(f1.z, c, a1.z); a1.w = fmaf(f1.w, c, a1.w);
}

// ---------------- init / degree ----------------
__global__ void zero_kernel(int N) {
    int i = blockIdx.x * blockDim.x + threadIdx.x;
    if (i < N) { g_deg[i] = 0; g_fill[i] = 0; }
    if (i < 4 * HID) g_stats[i] = 0.0f;
}

__global__ void deg_count(const int* __restrict__ dst, int E) {
    int i = blockIdx.x * blockDim.x + threadIdx.x;
    if (i < E) atomicAdd(&g_deg[dst[i]], 1);
}

// ---------------- weight fp16 round ----------------
__global__ void wsplit(const float* __restrict__ W1, const float* __restrict__ W2) {
    int i = blockIdx.x * blockDim.x + threadIdx.x;
    if (i < IN_DIM_C * HID) g_W1f[i] = __float2half_rn(W1[i]);
    if (i < HID * HID)      g_W2f[i] = __float2half_rn(W2[i]);
}

// ---------------- activation fp16 round (optionally fused BN+ReLU) ----------------
template<bool BNA>
__global__ __launch_bounds__(256) void convertA(const float* __restrict__ src,
                                                const float* __restrict__ ga,
                                                const float* __restrict__ bb,
                                                int total4, int kq) {   // kq = K/4
    int i = blockIdx.x * blockDim.x + threadIdx.x;
    if (i >= total4) return;
    float4 v = ((const float4*)src)[i];
    if (BNA) {
        int c4 = i % kq;
        float4 g = ((const float4*)ga)[c4];
        float4 b = ((const float4*)bb)[c4];
        v.x = fmaxf(0.f, fmaf(v.x, g.x, b.x));
        v.y = fmaxf(0.f, fmaf(v.y, g.y, b.y));
        v.z = fmaxf(0.f, fmaf(v.z, g.z, b.z));
        v.w = fmaxf(0.f, fmaf(v.w, g.w, b.w));
    }
    __half2 h01 = __floats2half2_rn(v.x, v.y);
    __half2 h23 = __floats2half2_rn(v.z, v.w);
    uint2 hp;
    hp.x = *(uint32_t*)&h01; hp.y = *(uint32_t*)&h23;
    ((uint2*)g_Ah)[i] = hp;
}

// ---------------- scan of g_deg -> g_rowp + dinv/invdeg (fused) ----------------
__global__ void scan1(int N) {
    __shared__ int s[256];
    int t = threadIdx.x;
    int i = blockIdx.x * 256 + t;
    int v = (i < N) ? g_deg[i] : 0;
    if (i < N) {
        float dg = (float)v + 1.0f;
        g_dinv[i]   = rsqrtf(dg);
        g_invdeg[i] = 1.0f / dg;
    }
    s[t] = v; __syncthreads();
    #pragma unroll
    for (int off = 1; off < 256; off <<= 1) {
        int x = (t >= off) ? s[t - off] : 0;
        __syncthreads();
        s[t] += x;
        __syncthreads();
    }
    if (i < N) g_rowp[i] = s[t] - v;             // exclusive
    if (t == 255) g_blksum[blockIdx.x] = s[t];
}
__global__ void scan2(int nb) {
    __shared__ int s[512];
    int t = threadIdx.x;
    int v = (t < nb) ? g_blksum[t] : 0;
    s[t] = v; __syncthreads();
    #pragma unroll
    for (int off = 1; off < 512; off <<= 1) {
        int x = (t >= off) ? s[t - off] : 0;
        __syncthreads();
        s[t] += x;
        __syncthreads();
    }
    g_blkoff[t] = s[t] - v;
}
__global__ void scan3(int N, int E) {
    int i = blockIdx.x * 256 + threadIdx.x;
    if (i < N) g_rowp[i] += g_blkoff[i >> 8];
    if (i == 0) g_rowp[N] = E;
}

// ---------------- CSR fill ----------------
__global__ void csr_fill(const int* __restrict__ src, const int* __restrict__ dst, int E) {
    int e = blockIdx.x * blockDim.x + threadIdx.x;
    if (e >= E) return;
    int s = src[e], d = dst[e];
    int pos = g_rowp[d] + atomicAdd(&g_fill[d], 1);
    g_esrc[pos]  = s;
    g_ecoef[pos] = g_dinv[s] * g_dinv[d];
}

// ---------------- tensor-core GEMM (plain fp16 x fp16, 3-stage cp.async) -------------
#define TBM 128
#define TBN 128
#define TBK 32
#define APAD 40      // row = 80B
#define BPAD 136     // row = 272B

#define LDSM4(R, addr) \
    asm volatile("ldmatrix.sync.aligned.m8n8.x4.shared.b16 {%0,%1,%2,%3}, [%4];" \
        : "=r"((R)[0]), "=r"((R)[1]), "=r"((R)[2]), "=r"((R)[3]) : "r"(addr))
#define LDSM4T(R, addr) \
    asm volatile("ldmatrix.sync.aligned.m8n8.x4.trans.shared.b16 {%0,%1,%2,%3}, [%4];" \
        : "=r"((R)[0]), "=r"((R)[1]), "=r"((R)[2]), "=r"((R)[3]) : "r"(addr))
#define MMA16816F(d, a, b0, b1) \
    asm volatile("mma.sync.aligned.m16n8k16.row.col.f32.f16.f16.f32 " \
        "{%0,%1,%2,%3},{%4,%5,%6,%7},{%8,%9},{%0,%1,%2,%3};" \
        : "+f"((d)[0]), "+f"((d)[1]), "+f"((d)[2]), "+f"((d)[3]) \
        : "r"((a)[0]), "r"((a)[1]), "r"((a)[2]), "r"((a)[3]), "r"(b0), "r"(b1))
#define CPASYNC16(dst, src, sz) \
    asm volatile("cp.async.cg.shared.global [%0], [%1], 16, %2;" \
        :: "r"(dst), "l"(src), "r"(sz) : "memory")
#define CPCOMMIT() asm volatile("cp.async.commit_group;" ::: "memory")

__global__ __launch_bounds__(256, 2) void mma_gemm(
    const __half* __restrict__ Ah,
    const __half* __restrict__ Bf,
    __half* __restrict__ Ch, int M, int K)
{
    __shared__ __half sA[3][TBM][APAD];
    __shared__ __half sB[3][TBK][BPAD];

    int tid = threadIdx.x;
    int warp = tid >> 5, lane = tid & 31;
    int wm = warp >> 2, wn = warp & 3;           // 2x4 warp grid, warp tile m64 x n32
    int block_row = blockIdx.x * TBM;
    int block_col = blockIdx.y * TBN;

    float acc[4][4][4];
    #pragma unroll
    for (int i = 0; i < 4; i++)
        #pragma unroll
        for (int j = 0; j < 4; j++)
            #pragma unroll
            for (int k = 0; k < 4; k++) acc[i][j][k] = 0.0f;

    auto issueStage = [&](int st, int k0) {
        // A tile: 128 rows x 32 fp16 (64B) -> 4 granules/row, 512 granules
        #pragma unroll
        for (int q = 0; q < 2; q++) {
            int g = tid * 2 + q;
            int row = g >> 2, c16 = g & 3;
            int grow = block_row + row;
            int sz = (grow < M) ? 16 : 0;
            const __half* ph = Ah + (size_t)grow * K + k0 + c16 * 8;
            uint32_t dh = (uint32_t)__cvta_generic_to_shared(&sA[st][row][c16 * 8]);
            CPASYNC16(dh, ph, sz);
        }
        // B tile: 32 rows x 128 fp16 (256B) -> 16 granules/row, 512 granules
        #pragma unroll
        for (int q = 0; q < 2; q++) {
            int g = tid * 2 + q;
            int row = g >> 4, c16 = g & 15;
            const __half* pb = Bf + (size_t)(k0 + row) * HID + block_col + c16 * 8;
            uint32_t db = (uint32_t)__cvta_generic_to_shared(&sB[st][row][c16 * 8]);
            CPASYNC16(db, pb, 16);
        }
    };

    auto mmaStage = [&](int st) {
        #pragma unroll
        for (int ks = 0; ks < 2; ks++) {
            uint32_t af[4][4], bf[2][4];
            #pragma unroll
            for (int mi = 0; mi < 4; mi++) {
                int r = wm * 64 + mi * 16 + (lane & 15);
                int c = ks * 16 + (lane >> 4) * 8;
                uint32_t ah = (uint32_t)__cvta_generic_to_shared(&sA[st][r][c]);
                LDSM4(af[mi], ah);
            }
            #pragma unroll
            for (int ni = 0; ni < 2; ni++) {
                int r = ks * 16 + (lane & 15);
                int c = wn * 32 + ni * 16 + (lane >> 4) * 8;
                uint32_t bb = (uint32_t)__cvta_generic_to_shared(&sB[st][r][c]);
                LDSM4T(bf[ni], bb);
            }
            #pragma unroll
            for (int mi = 0; mi < 4; mi++)
                #pragma unroll
                for (int n8 = 0; n8 < 4; n8++) {
                    uint32_t b0 = bf[n8 >> 1][(n8 & 1) * 2];
                    uint32_t b1 = bf[n8 >> 1][(n8 & 1) * 2 + 1];
                    MMA16816F(acc[mi][n8], af[mi], b0, b1);
                }
        }
    };

    int nIters = K / TBK;
    issueStage(0, 0);
    CPCOMMIT();
    issueStage(1, TBK);
    CPCOMMIT();

    for (int it = 0; it < nIters; it++) {
        int cur = it % 3;
        asm volatile("cp.async.wait_group 1;" ::: "memory");
        __syncthreads();
        mmaStage(cur);
        if (it + 2 < nIters) issueStage((it + 2) % 3, (it + 2) * TBK);
        CPCOMMIT();
    }

    // epilogue: write h as fp16
    #pragma unroll
    for (int mi = 0; mi < 4; mi++) {
        #pragma unroll
        for (int n8 = 0; n8 < 4; n8++) {
            int col = block_col + wn * 32 + n8 * 8 + (lane & 3) * 2;
            #pragma unroll
            for (int h = 0; h < 2; h++) {
                int row = block_row + wm * 64 + mi * 16 + (lane >> 2) + h * 8;
                if (row < M) {
                    *(__half2*)(Ch + (size_t)row * HID + col) =
                        __floats2half2_rn(acc[mi][n8][h * 2], acc[mi][n8][h * 2 + 1]);
                }
            }
        }
    }
}

// ---------------- pull aggregation + fused BN stats (fp16 gather, unroll-8) -----------
__global__ __launch_bounds__(256) void aggregate(
    const __half* __restrict__ h, const float* __restrict__ bias,
    float* __restrict__ agg, float* __restrict__ sum, float* __restrict__ sq, int N)
{
    int lane = threadIdx.x & 31;
    int w    = threadIdx.x >> 5;
    int wId  = (blockIdx.x << 3) + w;
    int nW   = gridDim.x << 3;

    float4 bv0 = ((const float4*)bias)[lane * 2];
    float4 bv1 = ((const float4*)bias)[lane * 2 + 1];
    float4 cs0 = make_float4(0,0,0,0), cq0 = make_float4(0,0,0,0);
    float4 cs1 = make_float4(0,0,0,0), cq1 = make_float4(0,0,0,0);

    for (int d = wId; d < N; d += nW) {
        int beg = g_rowp[d], end = g_rowp[d + 1];
        float id = g_invdeg[d];
        uint4 sv = ((const uint4*)(h + (size_t)d * HID))[lane];
        float4 a0 = bv0, a1 = bv1;
        fma8(sv, id, a0, a1);

        int j = beg;
        for (; j + 8 <= end; j += 8) {
            int   s0 = g_esrc[j],     s1 = g_esrc[j + 1];
            int   s2 = g_esrc[j + 2], s3 = g_esrc[j + 3];
            int   s4 = g_esrc[j + 4], s5 = g_esrc[j + 5];
            int   s6 = g_esrc[j + 6], s7 = g_esrc[j + 7];
            float c0 = g_ecoef[j],     c1 = g_ecoef[j + 1];
            float c2 = g_ecoef[j + 2], c3 = g_ecoef[j + 3];
            float c4 = g_ecoef[j + 4], c5 = g_ecoef[j + 5];
            float c6 = g_ecoef[j + 6], c7 = g_ecoef[j + 7];
            uint4 v0 = ((const uint4*)(h + (size_t)s0 * HID))[lane];
            uint4 v1 = ((const uint4*)(h + (size_t)s1 * HID))[lane];
            uint4 v2 = ((const uint4*)(h + (size_t)s2 * HID))[lane];
            uint4 v3 = ((const uint4*)(h + (size_t)s3 * HID))[lane];
            uint4 v4 = ((const uint4*)(h + (size_t)s4 * HID))[lane];
            uint4 v5 = ((const uint4*)(h + (size_t)s5 * HID))[lane];
            uint4 v6 = ((const uint4*)(h + (size_t)s6 * HID))[lane];
            uint4 v7 = ((const uint4*)(h + (size_t)s7 * HID))[lane];
            fma8(v0, c0, a0, a1); fma8(v1, c1, a0, a1);
            fma8(v2, c2, a0, a1); fma8(v3, c3, a0, a1);
            fma8(v4, c4, a0, a1); fma8(v5, c5, a0, a1);
            fma8(v6, c6, a0, a1); fma8(v7, c7, a0, a1);
        }
        for (; j + 4 <= end; j += 4) {
            int   s0 = g_esrc[j],     s1 = g_esrc[j + 1];
            int   s2 = g_esrc[j + 2], s3 = g_esrc[j + 3];
            float c0 = g_ecoef[j],     c1 = g_ecoef[j + 1];
            float c2 = g_ecoef[j + 2], c3 = g_ecoef[j + 3];
            uint4 v0 = ((const uint4*)(h + (size_t)s0 * HID))[lane];
            uint4 v1 = ((const uint4*)(h + (size_t)s1 * HID))[lane];
            uint4 v2 = ((const uint4*)(h + (size_t)s2 * HID))[lane];
            uint4 v3 = ((const uint4*)(h + (size_t)s3 * HID))[lane];
            fma8(v0, c0, a0, a1); fma8(v1, c1, a0, a1);
            fma8(v2, c2, a0, a1); fma8(v3, c3, a0, a1);
        }
        for (; j < end; j++) {
            int s  = g_esrc[j];
            float c = g_ecoef[j];
            uint4 v = ((const uint4*)(h + (size_t)s * HID))[lane];
            fma8(v, c, a0, a1);
        }

        float4* ad = (float4*)(agg + (size_t)d * HID);
        ad[lane * 2]     = a0;
        ad[lane * 2 + 1] = a1;
        f4acc(cs0, a0); f4accsq(cq0, a0);
        f4acc(cs1, a1); f4accsq(cq1, a1);
    }

    __shared__ float4 rs0[8][32], rq0[8][32], rs1[8][32], rq1[8][32];
    rs0[w][lane] = cs0; rq0[w][lane] = cq0;
    rs1[w][lane] = cs1; rq1[w][lane] = cq1;
    __syncthreads();
    if (w == 0) {
        float4 ts0 = rs0[0][lane], tq0 = rq0[0][lane];
        float4 ts1 = rs1[0][lane], tq1 = rq1[0][lane];
        #pragma unroll
        for (int i = 1; i < 8; i++) {
            f4acc(ts0, rs0[i][lane]); f4acc(tq0, rq0[i][lane]);
            f4acc(ts1, rs1[i][lane]); f4acc(tq1, rq1[i][lane]);
        }
        int c0 = lane * 8;
        atomicAdd(&sum[c0+0], ts0.x); atomicAdd(&sum[c0+1], ts0.y);
        atomicAdd(&sum[c0+2], ts0.z); atomicAdd(&sum[c0+3], ts0.w);
        atomicAdd(&sum[c0+4], ts1.x); atomicAdd(&sum[c0+5], ts1.y);
        atomicAdd(&sum[c0+6], ts1.z); atomicAdd(&sum[c0+7], ts1.w);
        atomicAdd(&sq[c0+0],  tq0.x); atomicAdd(&sq[c0+1],  tq0.y);
        atomicAdd(&sq[c0+2],  tq0.z); atomicAdd(&sq[c0+3],  tq0.w);
        atomicAdd(&sq[c0+4],  tq1.x); atomicAdd(&sq[c0+5],  tq1.y);
        atomicAdd(&sq[c0+6],  tq1.z); atomicAdd(&sq[c0+7],  tq1.w);
    }
}

// ---------------- BN coef (1 block) ----------------
__global__ void bn_coef(const float* __restrict__ sum, const float* __restrict__ sq,
                        const float* __restrict__ gamma, const float* __restrict__ beta,
                        float* __restrict__ ga, float* __restrict__ bb, int N) {
    int c = threadIdx.x;
    float invN = 1.0f / (float)N;
    float mu  = sum[c] * invN;
    float var = sq[c] * invN - mu * mu;
    float rs  = rsqrtf(var + BN_EPS);
    float g   = gamma[c] * rs;
    ga[c] = g;
    bb[c] = beta[c] - mu * g;
}

// ---------------- BN apply + ReLU (final output) ----------------
__global__ __launch_bounds__(256) void bn_apply2(float* __restrict__ a,
                                                 const float* __restrict__ ga,
                                                 const float* __restrict__ bb, int N) {
    int i = blockIdx.x * blockDim.x + threadIdx.x;
    int total = N * (HID / 4);
    if (i >= total) return;
    int c4 = i & 63;
    float4 v = ((float4*)a)[i];
    float4 g = ((const float4*)ga)[c4];
    float4 b = ((const float4*)bb)[c4];
    v.x = fmaxf(0.f, fmaf(v.x, g.x, b.x));
    v.y = fmaxf(0.f, fmaf(v.y, g.y, b.y));
    v.z = fmaxf(0.f, fmaf(v.z, g.z, b.z));
    v.w = fmaxf(0.f, fmaf(v.w, g.w, b.w));
    ((float4*)a)[i] = v;
}

// ---------------- launch (fork/join: CSR build ∥ convert+GEMM1) ----------------
extern "C" void kernel_launch(void* const* d_in, const int* in_sizes, int n_in,
                              void* d_out, int out_size) {
    const float* x   = (const float*)d_in[0];
    const int*   ei  = (const int*)d_in[1];
    const float* W1  = (const float*)d_in[2];
    const float* b1  = (const float*)d_in[3];
    const float* g1  = (const float*)d_in[4];
    const float* be1 = (const float*)d_in[5];
    const float* W2  = (const float*)d_in[6];
    const float* b2  = (const float*)d_in[7];
    const float* g2  = (const float*)d_in[8];
    const float* be2 = (const float*)d_in[9];
    float* out = (float*)d_out;

    const int IN_DIM = IN_DIM_C;
    int N = in_sizes[0] / IN_DIM;
    int E = in_sizes[1] / 2;
    const int* src = ei;
    const int* dst = ei + E;

    float *aP, *statsP, *coefP;
    cudaGetSymbolAddress((void**)&aP, g_a);
    cudaGetSymbolAddress((void**)&statsP, g_stats);
    cudaGetSymbolAddress((void**)&coefP, g_coef);
    __half *w1f, *w2f, *ahP, *hH;
    cudaGetSymbolAddress((void**)&w1f, g_W1f);
    cudaGetSymbolAddress((void**)&w2f, g_W2f);
    cudaGetSymbolAddress((void**)&ahP, g_Ah);
    cudaGetSymbolAddress((void**)&hH, g_hH);

    int nb256 = (N + 255) / 256;
    int aggBlocks  = 592;
    int outBlocks  = (N * (HID / 4) + 255) / 256;
    dim3 gemmGrid((N + TBM - 1) / TBM, HID / TBN);
    int cv1 = N * (IN_DIM / 4);
    int cv2 = N * (HID / 4);

    // side stream for the CSR build (host objects only; created/destroyed per call)
    cudaStream_t s2;
    cudaStreamCreateWithFlags(&s2, cudaStreamNonBlocking);
    cudaEvent_t eFork, eJoin;
    cudaEventCreateWithFlags(&eFork, cudaEventDisableTiming);
    cudaEventCreateWithFlags(&eJoin, cudaEventDisableTiming);

    // fork
    cudaEventRecord(eFork, 0);
    cudaStreamWaitEvent(s2, eFork, 0);

    // ---- branch B (s2): graph structure + CSR ----
    zero_kernel<<<nb256, 256, 0, s2>>>(N);
    deg_count<<<(E + 255) / 256, 256, 0, s2>>>(dst, E);
    scan1<<<nb256, 256, 0, s2>>>(N);
    scan2<<<1, 512, 0, s2>>>(nb256);
    scan3<<<(N + 256) / 256, 256, 0, s2>>>(N, E);
    csr_fill<<<(E + 255) / 256, 256, 0, s2>>>(src, dst, E);
    cudaEventRecord(eJoin, s2);

    // ---- branch A (default stream): weights + convert + GEMM1 ----
    wsplit<<<(IN_DIM * HID + 255) / 256, 256>>>(W1, W2);
    convertA<false><<<(cv1 + 255) / 256, 256>>>(x, nullptr, nullptr, cv1, IN_DIM / 4);
    mma_gemm<<<gemmGrid, 256>>>(ahP, w1f, hH, N, IN_DIM);

    // join before aggregation (needs CSR + stats zero + invdeg)
    cudaStreamWaitEvent(0, eJoin, 0);

    // ---- layer 1 ----
    aggregate<<<aggBlocks, 256>>>(hH, b1, aP, statsP + 0, statsP + HID, N);
    bn_coef<<<1, 256>>>(statsP + 0, statsP + HID, g1, be1, coefP + 0, coefP + HID, N);

    // ---- layer 2 (BN1+ReLU fused into convert) ----
    convertA<true><<<(cv2 + 255) / 256, 256>>>(aP, coefP + 0, coefP + HID, cv2, HID / 4);
    mma_gemm<<<gemmGrid, 256>>>(ahP, w2f, hH, N, HID);
    aggregate<<<aggBlocks, 256>>>(hH, b2, out, statsP + 2 * HID, statsP + 3 * HID, N);
    bn_coef<<<1, 256>>>(statsP + 2 * HID, statsP + 3 * HID, g2, be2,
                        coefP + 2 * HID, coefP + 3 * HID, N);
    bn_apply2<<<outBlocks, 256>>>(out, coefP + 2 * HID, coefP + 3 * HID, N);

    cudaEventDestroy(eFork);
    cudaEventDestroy(eJoin);
    cudaStreamDestroy(s2);
}